// round 1
// baseline (speedup 1.0000x reference)
#include <cuda_runtime.h>
#include <cstddef>

// Problem constants
#define cH   128
#define cNU  200000
#define cNM  80000
#define cE   2000000
#define cEL  500000
#define cFD  512

// ---------------- scratch (device globals; no allocation allowed) ----------------
__device__ float g_movie_x[(size_t)cNM * cH];
__device__ float g_movie_h[(size_t)cNM * cH];
__device__ float g_user_h [(size_t)cNU * cH];
__device__ float g_aggU1 [(size_t)cNU * cH];
__device__ float g_aggU2 [(size_t)cNU * cH];
__device__ float g_aggM2 [(size_t)cNM * cH];
__device__ float g_movie_o[(size_t)cNM * cH];
__device__ float g_user_o [(size_t)cNU * cH];
__device__ int   g_deg_u[cNU];
__device__ int   g_deg_m[cNM];
__device__ float g_vecs[2 * cH];   // [0:128) vsel = user_init@Wl1_um ; [128:256) cb1 = bl1_mu + user_init@Wr1_mu

// ---------------- helpers ----------------
__device__ __forceinline__ void red_add_v4(float* p, float4 v) {
    asm volatile("red.global.add.v4.f32 [%0], {%1, %2, %3, %4};"
                 :: "l"(p), "f"(v.x), "f"(v.y), "f"(v.z), "f"(v.w) : "memory");
}

__global__ void zero_f4_kernel(float4* p, size_t n4) {
    size_t i = (size_t)blockIdx.x * blockDim.x + threadIdx.x;
    size_t stride = (size_t)gridDim.x * blockDim.x;
    float4 z = make_float4(0.f, 0.f, 0.f, 0.f);
    for (; i < n4; i += stride) p[i] = z;
}

__global__ void deg_kernel(const int* __restrict__ src, const int* __restrict__ dst,
                           int* __restrict__ du, int* __restrict__ dm, int E) {
    int i = blockIdx.x * blockDim.x + threadIdx.x;
    int stride = gridDim.x * blockDim.x;
    for (; i < E; i += stride) {
        atomicAdd(&du[src[i]], 1);
        atomicAdd(&dm[dst[i]], 1);
    }
}

// vsel = user_init @ Wl1_um ; cb1 = bl1_mu + user_init @ Wr1_mu
__global__ void vec_kernel(const float* __restrict__ user_init,
                           const float* __restrict__ Wl1_um,
                           const float* __restrict__ Wr1_mu,
                           const float* __restrict__ bl1_mu,
                           float* __restrict__ vecs) {
    int j = threadIdx.x;
    if (j >= cH) return;
    float s1 = 0.f, s2 = 0.f;
    for (int k = 0; k < cH; k++) {
        float u = user_init[k];
        s1 = fmaf(u, Wl1_um[k * cH + j], s1);
        s2 = fmaf(u, Wr1_mu[k * cH + j], s2);
    }
    vecs[j]      = s1;
    vecs[cH + j] = bl1_mu[j] + s2;
}

// ---------------- unified SGEMM: C[M,128] = concat(A1*rowscale?, A2)[M,K] @ stack(B1,B2)[K,128] + bias (+sel) (+relu)
#define BK 16
template<bool SCALE_A1, bool BIAS_SEL, bool RELU>
__global__ void __launch_bounds__(256)
gemm128_kernel(const float* __restrict__ A1, const float* __restrict__ A2,
               const float* __restrict__ B1, const float* __restrict__ B2,
               float* __restrict__ C,
               const float* __restrict__ bias,   // [128]
               const float* __restrict__ vsel,   // [128] (BIAS_SEL only)
               const int*   __restrict__ deg,    // per-row (SCALE_A1 / BIAS_SEL)
               int M, int KT1, int KT2) {
    __shared__ float As[BK][132];
    __shared__ float Bs[BK][128];
    __shared__ float sScale[128];
    __shared__ float sBias[128];
    __shared__ float sVsel[128];

    const int tid = threadIdx.x;
    const int m0  = blockIdx.x * 128;
    const int lda1 = KT1 * BK;
    const int lda2 = KT2 * BK;

    if (tid < 128) {
        sBias[tid] = bias[tid];
        if (BIAS_SEL) sVsel[tid] = vsel[tid];
        if (SCALE_A1) {
            int m = m0 + tid;
            int d = (m < M) ? deg[m] : 1;
            if (d < 1) d = 1;
            sScale[tid] = 1.0f / (float)d;
        }
    }
    __syncthreads();

    float acc[8][8];
    #pragma unroll
    for (int i = 0; i < 8; i++)
        #pragma unroll
        for (int j = 0; j < 8; j++) acc[i][j] = 0.f;

    const int tr = (tid >> 4) << 3;   // output row offset in tile
    const int tc = (tid & 15) << 3;   // output col offset

    const int KT = KT1 + KT2;
    for (int t = 0; t < KT; t++) {
        const bool first = (t < KT1);
        // ---- load A tile (128 x 16), transposed into As[k][m]
        #pragma unroll
        for (int i = 0; i < 2; i++) {
            int f = tid + i * 256;            // 0..511
            int row = f >> 2;
            int c4  = (f & 3) << 2;
            int m = m0 + row;
            float4 v = make_float4(0.f, 0.f, 0.f, 0.f);
            if (m < M) {
                const float* p = first ? (A1 + (size_t)m * lda1 + t * BK + c4)
                                       : (A2 + (size_t)m * lda2 + (t - KT1) * BK + c4);
                v = *(const float4*)p;
                if (SCALE_A1 && first) {
                    float s = sScale[row];
                    v.x *= s; v.y *= s; v.z *= s; v.w *= s;
                }
            }
            As[c4 + 0][row] = v.x;
            As[c4 + 1][row] = v.y;
            As[c4 + 2][row] = v.z;
            As[c4 + 3][row] = v.w;
        }
        // ---- load B tile (16 x 128)
        #pragma unroll
        for (int i = 0; i < 2; i++) {
            int f = tid + i * 256;            // 0..511
            int row = f >> 5;
            int n4  = (f & 31) << 2;
            const float* p = first ? (B1 + (size_t)(t * BK + row) * 128 + n4)
                                   : (B2 + (size_t)((t - KT1) * BK + row) * 128 + n4);
            *(float4*)&Bs[row][n4] = *(const float4*)p;
        }
        __syncthreads();

        #pragma unroll
        for (int k = 0; k < BK; k++) {
            float a[8], b[8];
            #pragma unroll
            for (int i = 0; i < 8; i++) a[i] = As[k][tr + i];
            #pragma unroll
            for (int j = 0; j < 8; j++) b[j] = Bs[k][tc + j];
            #pragma unroll
            for (int i = 0; i < 8; i++)
                #pragma unroll
                for (int j = 0; j < 8; j++)
                    acc[i][j] = fmaf(a[i], b[j], acc[i][j]);
        }
        __syncthreads();
    }

    // ---- epilogue
    #pragma unroll
    for (int i = 0; i < 8; i++) {
        int m = m0 + tr + i;
        if (m >= M) continue;
        float sel = 0.f;
        if (BIAS_SEL) sel = (deg[m] > 0) ? 1.f : 0.f;
        #pragma unroll
        for (int j0 = 0; j0 < 8; j0 += 4) {
            float4 o;
            float* ov = &o.x;
            #pragma unroll
            for (int j = 0; j < 4; j++) {
                float c = acc[i][j0 + j] + sBias[tc + j0 + j];
                if (BIAS_SEL) c += sel * sVsel[tc + j0 + j];
                if (RELU) c = fmaxf(c, 0.f);
                ov[j] = c;
            }
            *(float4*)&C[(size_t)m * 128 + tc + j0] = o;
        }
    }
}

// ---------------- fused edge pass 1: aggU1[src] += movie_x[dst]; aggU2[src] += movie_h[dst]
__global__ void edge_pass1_kernel(const int* __restrict__ src, const int* __restrict__ dst,
                                  const float* __restrict__ mx, const float* __restrict__ mh,
                                  float* __restrict__ aU1, float* __restrict__ aU2, int E) {
    int w    = (blockIdx.x * blockDim.x + threadIdx.x) >> 5;
    int lane = threadIdx.x & 31;
    int nw   = (gridDim.x * blockDim.x) >> 5;
    for (int e = w; e < E; e += nw) {
        int s = src[e];
        int d = dst[e];
        float4 v1 = ((const float4*)(mx + (size_t)d * 128))[lane];
        float4 v2 = ((const float4*)(mh + (size_t)d * 128))[lane];
        red_add_v4(aU1 + (size_t)s * 128 + lane * 4, v1);
        red_add_v4(aU2 + (size_t)s * 128 + lane * 4, v2);
    }
}

// ---------------- edge pass 2: aggM2[dst] += user_h[src]
__global__ void edge_pass2_kernel(const int* __restrict__ src, const int* __restrict__ dst,
                                  const float* __restrict__ uh,
                                  float* __restrict__ aM2, int E) {
    int w    = (blockIdx.x * blockDim.x + threadIdx.x) >> 5;
    int lane = threadIdx.x & 31;
    int nw   = (gridDim.x * blockDim.x) >> 5;
    for (int e = w; e < E; e += nw) {
        int s = src[e];
        int d = dst[e];
        float4 v = ((const float4*)(uh + (size_t)s * 128))[lane];
        red_add_v4(aM2 + (size_t)d * 128 + lane * 4, v);
    }
}

// ---------------- final edge dot products
__global__ void dot_kernel(const int* __restrict__ lu, const int* __restrict__ lm,
                           const float* __restrict__ U, const float* __restrict__ Mo,
                           float* __restrict__ out, int EL) {
    int w    = (blockIdx.x * blockDim.x + threadIdx.x) >> 5;
    int lane = threadIdx.x & 31;
    int nw   = (gridDim.x * blockDim.x) >> 5;
    for (int i = w; i < EL; i += nw) {
        int u = lu[i];
        int m = lm[i];
        float4 a = ((const float4*)(U  + (size_t)u * 128))[lane];
        float4 b = ((const float4*)(Mo + (size_t)m * 128))[lane];
        float p = a.x * b.x + a.y * b.y + a.z * b.z + a.w * b.w;
        #pragma unroll
        for (int off = 16; off > 0; off >>= 1)
            p += __shfl_xor_sync(0xFFFFFFFFu, p, off);
        if (lane == 0) out[i] = p;
    }
}

// ---------------- launch ----------------
extern "C" void kernel_launch(void* const* d_in, const int* in_sizes, int n_in,
                              void* d_out, int out_size) {
    const float* movie_feats = (const float*)d_in[0];
    const float* user_init   = (const float*)d_in[1];
    const int*   edge_src    = (const int*)d_in[2];
    const int*   edge_dst    = (const int*)d_in[3];
    const int*   lbl_user    = (const int*)d_in[4];
    const int*   lbl_movie   = (const int*)d_in[5];
    const int wi = (n_in >= 21) ? 7 : 6;   // skip scalar n_users if present
    const float* Wm     = (const float*)d_in[wi + 0];
    const float* bm     = (const float*)d_in[wi + 1];
    const float* Wl1_um = (const float*)d_in[wi + 2];
    const float* bl1_um = (const float*)d_in[wi + 3];
    const float* Wr1_um = (const float*)d_in[wi + 4];
    const float* Wl1_mu = (const float*)d_in[wi + 5];
    const float* bl1_mu = (const float*)d_in[wi + 6];
    const float* Wr1_mu = (const float*)d_in[wi + 7];
    const float* Wl2_um = (const float*)d_in[wi + 8];
    const float* bl2_um = (const float*)d_in[wi + 9];
    const float* Wr2_um = (const float*)d_in[wi + 10];
    const float* Wl2_mu = (const float*)d_in[wi + 11];
    const float* bl2_mu = (const float*)d_in[wi + 12];
    const float* Wr2_mu = (const float*)d_in[wi + 13];
    float* out = (float*)d_out;

    // resolve scratch symbols (pure lookup; capture-safe)
    float *movie_x, *movie_h, *user_h, *aggU1, *aggU2, *aggM2, *movie_o, *user_o, *vecs;
    int *deg_u, *deg_m;
    cudaGetSymbolAddress((void**)&movie_x, g_movie_x);
    cudaGetSymbolAddress((void**)&movie_h, g_movie_h);
    cudaGetSymbolAddress((void**)&user_h,  g_user_h);
    cudaGetSymbolAddress((void**)&aggU1,   g_aggU1);
    cudaGetSymbolAddress((void**)&aggU2,   g_aggU2);
    cudaGetSymbolAddress((void**)&aggM2,   g_aggM2);
    cudaGetSymbolAddress((void**)&movie_o, g_movie_o);
    cudaGetSymbolAddress((void**)&user_o,  g_user_o);
    cudaGetSymbolAddress((void**)&vecs,    g_vecs);
    cudaGetSymbolAddress((void**)&deg_u,   g_deg_u);
    cudaGetSymbolAddress((void**)&deg_m,   g_deg_m);

    const int ZB = 4096, ZT = 256;
    // zero accumulators + degree counters
    zero_f4_kernel<<<ZB, ZT>>>((float4*)aggU1, (size_t)cNU * cH / 4);
    zero_f4_kernel<<<ZB, ZT>>>((float4*)aggU2, (size_t)cNU * cH / 4);
    zero_f4_kernel<<<ZB, ZT>>>((float4*)aggM2, (size_t)cNM * cH / 4);
    zero_f4_kernel<<<256, ZT>>>((float4*)deg_u, (size_t)cNU / 4);
    zero_f4_kernel<<<256, ZT>>>((float4*)deg_m, (size_t)cNM / 4);

    deg_kernel<<<2048, 256>>>(edge_src, edge_dst, deg_u, deg_m, cE);
    vec_kernel<<<1, 128>>>(user_init, Wl1_um, Wr1_mu, bl1_mu, vecs);

    // (a) movie_x = movie_feats @ Wm + bm
    gemm128_kernel<false, false, false><<<(cNM + 127) / 128, 256>>>(
        movie_feats, nullptr, Wm, nullptr, movie_x, bm, nullptr, nullptr, cNM, cFD / BK, 0);

    // (b) movie_h = relu(movie_x @ Wr1_um + bl1_um + (deg_m>0)*vsel)
    gemm128_kernel<false, true, true><<<(cNM + 127) / 128, 256>>>(
        movie_x, nullptr, Wr1_um, nullptr, movie_h, bl1_um, vecs, deg_m, cNM, cH / BK, 0);

    // fused edge pass: aggU1 += movie_x[dst] ; aggU2 += movie_h[dst]  (scatter by src/user)
    edge_pass1_kernel<<<4736, 256>>>(edge_src, edge_dst, movie_x, movie_h, aggU1, aggU2, cE);

    // (c) user_h = relu((aggU1/deg_u) @ Wl1_mu + cb1)
    gemm128_kernel<true, false, true><<<(cNU + 127) / 128, 256>>>(
        aggU1, nullptr, Wl1_mu, nullptr, user_h, vecs + cH, nullptr, deg_u, cNU, cH / BK, 0);

    // edge pass 2: aggM2[dst] += user_h[src]
    edge_pass2_kernel<<<4736, 256>>>(edge_src, edge_dst, user_h, aggM2, cE);

    // (d) movie_o = (aggM2/deg_m) @ Wl2_um + bl2_um + movie_h @ Wr2_um
    gemm128_kernel<true, false, false><<<(cNM + 127) / 128, 256>>>(
        aggM2, movie_h, Wl2_um, Wr2_um, movie_o, bl2_um, nullptr, deg_m, cNM, cH / BK, cH / BK);

    // (e) user_o = (aggU2/deg_u) @ Wl2_mu + bl2_mu + user_h @ Wr2_mu
    gemm128_kernel<true, false, false><<<(cNU + 127) / 128, 256>>>(
        aggU2, user_h, Wl2_mu, Wr2_mu, user_o, bl2_mu, nullptr, deg_u, cNU, cH / BK, cH / BK);

    // final dot products
    dot_kernel<<<4736, 256>>>(lbl_user, lbl_movie, user_o, movie_o, out, cEL);

    (void)in_sizes; (void)out_size;
}

// round 2
// speedup vs baseline: 1.3762x; 1.3762x over previous
#include <cuda_runtime.h>
#include <cstddef>

// Problem constants
#define cH   128
#define cNU  200000
#define cNM  80000
#define cE   2000000
#define cEL  500000
#define cFD  512

// ---------------- scratch (device globals; no allocation allowed) ----------------
__device__ float g_movie_x[(size_t)cNM * cH];
__device__ float g_movie_h[(size_t)cNM * cH];
__device__ float g_user_h [(size_t)cNU * cH];
__device__ float g_aggU1 [(size_t)cNU * cH];   // mean of movie_x over user's edges
__device__ float g_aggU2 [(size_t)cNU * cH];   // mean of movie_h over user's edges
__device__ float g_aggM2 [(size_t)cNM * cH];   // mean of user_h over movie's edges
__device__ float g_movie_o[(size_t)cNM * cH];
__device__ float g_user_o [(size_t)cNU * cH];
__device__ int   g_deg_u[cNU];
__device__ int   g_deg_m[cNM];
__device__ int   g_offU[cNU + 1];
__device__ int   g_offM[cNM + 1];
__device__ int   g_curU[cNU];
__device__ int   g_curM[cNM];
__device__ int   g_csrU[cE];   // movie id per user-sorted edge
__device__ int   g_csrM[cE];   // user id per movie-sorted edge
__device__ float g_vecs[2 * cH];   // [0:128) vsel = user_init@Wl1_um ; [128:256) cb1 = bl1_mu + user_init@Wr1_mu

// ---------------- small utility kernels ----------------
__global__ void zero_i_kernel(int* p, int n) {
    int i = blockIdx.x * blockDim.x + threadIdx.x;
    int stride = gridDim.x * blockDim.x;
    for (; i < n; i += stride) p[i] = 0;
}

__global__ void deg_kernel(const int* __restrict__ src, const int* __restrict__ dst,
                           int* __restrict__ du, int* __restrict__ dm, int E) {
    int i = blockIdx.x * blockDim.x + threadIdx.x;
    int stride = gridDim.x * blockDim.x;
    for (; i < E; i += stride) {
        atomicAdd(&du[src[i]], 1);
        atomicAdd(&dm[dst[i]], 1);
    }
}

// exclusive prefix scan: block 0 -> users, block 1 -> movies. blockDim = 1024.
__global__ void scan_kernel(const int* __restrict__ degU, int* __restrict__ offU, int* __restrict__ curU,
                            const int* __restrict__ degM, int* __restrict__ offM, int* __restrict__ curM) {
    const int* deg; int* off; int* cur; int n;
    if (blockIdx.x == 0) { deg = degU; off = offU; cur = curU; n = cNU; }
    else                 { deg = degM; off = offM; cur = curM; n = cNM; }

    __shared__ int wsum[32];
    __shared__ int carry_s;
    int tid = threadIdx.x, lane = tid & 31, wid = tid >> 5;
    if (tid == 0) carry_s = 0;
    __syncthreads();

    for (int base = 0; base < n; base += 1024) {
        int i = base + tid;
        int v = (i < n) ? deg[i] : 0;
        int x = v;
        #pragma unroll
        for (int o = 1; o < 32; o <<= 1) {
            int t = __shfl_up_sync(0xffffffffu, x, o);
            if (lane >= o) x += t;
        }
        if (lane == 31) wsum[wid] = x;
        __syncthreads();
        if (wid == 0) {
            int s = wsum[lane];
            #pragma unroll
            for (int o = 1; o < 32; o <<= 1) {
                int t = __shfl_up_sync(0xffffffffu, s, o);
                if (lane >= o) s += t;
            }
            wsum[lane] = s;
        }
        __syncthreads();
        int carry = carry_s;
        int wofs = (wid > 0) ? wsum[wid - 1] : 0;
        int excl = carry + wofs + x - v;
        if (i < n) { off[i] = excl; cur[i] = excl; }
        __syncthreads();
        if (tid == 0) carry_s += wsum[31];
        __syncthreads();
    }
    if (threadIdx.x == 0) off[n] = carry_s;
}

__global__ void scatter_kernel(const int* __restrict__ src, const int* __restrict__ dst,
                               int* __restrict__ curU, int* __restrict__ curM,
                               int* __restrict__ csrU, int* __restrict__ csrM, int E) {
    int i = blockIdx.x * blockDim.x + threadIdx.x;
    int stride = gridDim.x * blockDim.x;
    for (; i < E; i += stride) {
        int s = src[i];
        int d = dst[i];
        int p = atomicAdd(&curU[s], 1);
        csrU[p] = d;
        int q = atomicAdd(&curM[d], 1);
        csrM[q] = s;
    }
}

// vsel = user_init @ Wl1_um ; cb1 = bl1_mu + user_init @ Wr1_mu
__global__ void vec_kernel(const float* __restrict__ user_init,
                           const float* __restrict__ Wl1_um,
                           const float* __restrict__ Wr1_mu,
                           const float* __restrict__ bl1_mu,
                           float* __restrict__ vecs) {
    int j = threadIdx.x;
    if (j >= cH) return;
    float s1 = 0.f, s2 = 0.f;
    for (int k = 0; k < cH; k++) {
        float u = user_init[k];
        s1 = fmaf(u, Wl1_um[k * cH + j], s1);
        s2 = fmaf(u, Wr1_mu[k * cH + j], s2);
    }
    vecs[j]      = s1;
    vecs[cH + j] = bl1_mu[j] + s2;
}

// ---------------- CSR gather aggregations ----------------
// aggU1[u] = mean_{e in u} movie_x[csrU[e]] ; aggU2[u] = mean movie_h[csrU[e]]
__global__ void agg_user_kernel(const int* __restrict__ off, const int* __restrict__ csr,
                                const float* __restrict__ mx, const float* __restrict__ mh,
                                float* __restrict__ aU1, float* __restrict__ aU2, int NU) {
    int w    = (blockIdx.x * blockDim.x + threadIdx.x) >> 5;
    int lane = threadIdx.x & 31;
    int nw   = (gridDim.x * blockDim.x) >> 5;
    for (int u = w; u < NU; u += nw) {
        int s = off[u], e = off[u + 1];
        float4 a1 = make_float4(0.f, 0.f, 0.f, 0.f);
        float4 a2 = make_float4(0.f, 0.f, 0.f, 0.f);
        float4 a3 = make_float4(0.f, 0.f, 0.f, 0.f);
        float4 a4 = make_float4(0.f, 0.f, 0.f, 0.f);
        int i = s;
        for (; i + 1 < e; i += 2) {
            int d0 = csr[i];
            int d1 = csr[i + 1];
            float4 v0 = ((const float4*)(mx + (size_t)d0 * 128))[lane];
            float4 w0 = ((const float4*)(mh + (size_t)d0 * 128))[lane];
            float4 v1 = ((const float4*)(mx + (size_t)d1 * 128))[lane];
            float4 w1 = ((const float4*)(mh + (size_t)d1 * 128))[lane];
            a1.x += v0.x; a1.y += v0.y; a1.z += v0.z; a1.w += v0.w;
            a2.x += w0.x; a2.y += w0.y; a2.z += w0.z; a2.w += w0.w;
            a3.x += v1.x; a3.y += v1.y; a3.z += v1.z; a3.w += v1.w;
            a4.x += w1.x; a4.y += w1.y; a4.z += w1.z; a4.w += w1.w;
        }
        if (i < e) {
            int d0 = csr[i];
            float4 v0 = ((const float4*)(mx + (size_t)d0 * 128))[lane];
            float4 w0 = ((const float4*)(mh + (size_t)d0 * 128))[lane];
            a1.x += v0.x; a1.y += v0.y; a1.z += v0.z; a1.w += v0.w;
            a2.x += w0.x; a2.y += w0.y; a2.z += w0.z; a2.w += w0.w;
        }
        float sc = (e > s) ? 1.f / (float)(e - s) : 0.f;
        float4 o1 = make_float4((a1.x + a3.x) * sc, (a1.y + a3.y) * sc, (a1.z + a3.z) * sc, (a1.w + a3.w) * sc);
        float4 o2 = make_float4((a2.x + a4.x) * sc, (a2.y + a4.y) * sc, (a2.z + a4.z) * sc, (a2.w + a4.w) * sc);
        ((float4*)(aU1 + (size_t)u * 128))[lane] = o1;
        ((float4*)(aU2 + (size_t)u * 128))[lane] = o2;
    }
}

// aggM2[m] = mean_{e in m} user_h[csrM[e]]
__global__ void agg_movie_kernel(const int* __restrict__ off, const int* __restrict__ csr,
                                 const float* __restrict__ uh,
                                 float* __restrict__ aM2, int NM) {
    int w    = (blockIdx.x * blockDim.x + threadIdx.x) >> 5;
    int lane = threadIdx.x & 31;
    int nw   = (gridDim.x * blockDim.x) >> 5;
    for (int m = w; m < NM; m += nw) {
        int s = off[m], e = off[m + 1];
        float4 a1 = make_float4(0.f, 0.f, 0.f, 0.f);
        float4 a2 = make_float4(0.f, 0.f, 0.f, 0.f);
        int i = s;
        for (; i + 1 < e; i += 2) {
            int d0 = csr[i];
            int d1 = csr[i + 1];
            float4 v0 = ((const float4*)(uh + (size_t)d0 * 128))[lane];
            float4 v1 = ((const float4*)(uh + (size_t)d1 * 128))[lane];
            a1.x += v0.x; a1.y += v0.y; a1.z += v0.z; a1.w += v0.w;
            a2.x += v1.x; a2.y += v1.y; a2.z += v1.z; a2.w += v1.w;
        }
        if (i < e) {
            int d0 = csr[i];
            float4 v0 = ((const float4*)(uh + (size_t)d0 * 128))[lane];
            a1.x += v0.x; a1.y += v0.y; a1.z += v0.z; a1.w += v0.w;
        }
        float sc = (e > s) ? 1.f / (float)(e - s) : 0.f;
        float4 o = make_float4((a1.x + a2.x) * sc, (a1.y + a2.y) * sc, (a1.z + a2.z) * sc, (a1.w + a2.w) * sc);
        ((float4*)(aM2 + (size_t)m * 128))[lane] = o;
    }
}

// ---------------- SGEMM: C[M,128] = concat(A1,A2)[M,K] @ stack(B1,B2)[K,128] + bias (+sel*vsel) (+relu)
// Double-buffered smem, one sync per K-tile, float4 smem reads.
#define BK 16
template<bool BIAS_SEL, bool RELU>
__global__ void __launch_bounds__(256)
gemm128_kernel(const float* __restrict__ A1, const float* __restrict__ A2,
               const float* __restrict__ B1, const float* __restrict__ B2,
               float* __restrict__ C,
               const float* __restrict__ bias,   // [128]
               const float* __restrict__ vsel,   // [128] (BIAS_SEL only)
               const int*   __restrict__ deg,    // per-row (BIAS_SEL only)
               int M, int KT1, int KT2) {
    __shared__ float As[2][BK][132];
    __shared__ float Bs[2][BK][128];
    __shared__ float sBias[128];
    __shared__ float sVsel[128];

    const int tid = threadIdx.x;
    const int m0  = blockIdx.x * 128;
    const int lda1 = KT1 * BK;
    const int lda2 = KT2 * BK;
    const int KT = KT1 + KT2;

    if (tid < 128) {
        sBias[tid] = bias[tid];
        if (BIAS_SEL) sVsel[tid] = vsel[tid];
    }

    // per-thread load coordinates
    const int arow0 = tid >> 2;               // A rows: tid and tid+256 -> rows 0..127
    const int ac4   = (tid & 3) << 2;
    const int brow0 = tid >> 5;
    const int bn4   = (tid & 31) << 2;

    float4 rA[2], rB[2];

    auto loadTile = [&](int t, float4 (&a)[2], float4 (&b)[2]) {
        const bool first = (t < KT1);
        #pragma unroll
        for (int i = 0; i < 2; i++) {
            int row = arow0 + i * 64;
            int m = m0 + row;
            float4 v = make_float4(0.f, 0.f, 0.f, 0.f);
            if (m < M) {
                const float* p = first ? (A1 + (size_t)m * lda1 + t * BK + ac4)
                                       : (A2 + (size_t)m * lda2 + (t - KT1) * BK + ac4);
                v = *(const float4*)p;
            }
            a[i] = v;
        }
        #pragma unroll
        for (int i = 0; i < 2; i++) {
            int row = brow0 + i * 8;
            const float* p = first ? (B1 + (size_t)(t * BK + row) * 128 + bn4)
                                   : (B2 + (size_t)((t - KT1) * BK + row) * 128 + bn4);
            b[i] = *(const float4*)p;
        }
    };
    auto storeTile = [&](int buf, const float4 (&a)[2], const float4 (&b)[2]) {
        #pragma unroll
        for (int i = 0; i < 2; i++) {
            int row = arow0 + i * 64;
            As[buf][ac4 + 0][row] = a[i].x;
            As[buf][ac4 + 1][row] = a[i].y;
            As[buf][ac4 + 2][row] = a[i].z;
            As[buf][ac4 + 3][row] = a[i].w;
        }
        #pragma unroll
        for (int i = 0; i < 2; i++) {
            int row = brow0 + i * 8;
            *(float4*)&Bs[buf][row][bn4] = b[i];
        }
    };

    float acc[8][8];
    #pragma unroll
    for (int i = 0; i < 8; i++)
        #pragma unroll
        for (int j = 0; j < 8; j++) acc[i][j] = 0.f;

    const int tr = (tid >> 4) << 3;   // output row offset in tile (0..120)
    const int tc = (tid & 15) << 3;   // output col offset (0..120)

    loadTile(0, rA, rB);
    storeTile(0, rA, rB);
    __syncthreads();

    for (int t = 0; t < KT; t++) {
        const int cb = t & 1;
        if (t + 1 < KT) loadTile(t + 1, rA, rB);

        #pragma unroll
        for (int k = 0; k < BK; k++) {
            float4 a0 = *(const float4*)&As[cb][k][tr];
            float4 a1 = *(const float4*)&As[cb][k][tr + 4];
            float4 b0 = *(const float4*)&Bs[cb][k][tc];
            float4 b1 = *(const float4*)&Bs[cb][k][tc + 4];
            float a[8] = {a0.x, a0.y, a0.z, a0.w, a1.x, a1.y, a1.z, a1.w};
            float b[8] = {b0.x, b0.y, b0.z, b0.w, b1.x, b1.y, b1.z, b1.w};
            #pragma unroll
            for (int i = 0; i < 8; i++)
                #pragma unroll
                for (int j = 0; j < 8; j++)
                    acc[i][j] = fmaf(a[i], b[j], acc[i][j]);
        }
        if (t + 1 < KT) storeTile((t + 1) & 1, rA, rB);
        __syncthreads();
    }

    // ---- epilogue
    #pragma unroll
    for (int i = 0; i < 8; i++) {
        int m = m0 + tr + i;
        if (m >= M) continue;
        float sel = 0.f;
        if (BIAS_SEL) sel = (deg[m] > 0) ? 1.f : 0.f;
        #pragma unroll
        for (int j0 = 0; j0 < 8; j0 += 4) {
            float4 o;
            float* ov = &o.x;
            #pragma unroll
            for (int j = 0; j < 4; j++) {
                float c = acc[i][j0 + j] + sBias[tc + j0 + j];
                if (BIAS_SEL) c += sel * sVsel[tc + j0 + j];
                if (RELU) c = fmaxf(c, 0.f);
                ov[j] = c;
            }
            *(float4*)&C[(size_t)m * 128 + tc + j0] = o;
        }
    }
}

// ---------------- final edge dot products ----------------
__global__ void dot_kernel(const int* __restrict__ lu, const int* __restrict__ lm,
                           const float* __restrict__ U, const float* __restrict__ Mo,
                           float* __restrict__ out, int EL) {
    int w    = (blockIdx.x * blockDim.x + threadIdx.x) >> 5;
    int lane = threadIdx.x & 31;
    int nw   = (gridDim.x * blockDim.x) >> 5;
    for (int i = w; i < EL; i += nw) {
        int u = lu[i];
        int m = lm[i];
        float4 a = ((const float4*)(U  + (size_t)u * 128))[lane];
        float4 b = ((const float4*)(Mo + (size_t)m * 128))[lane];
        float p = a.x * b.x + a.y * b.y + a.z * b.z + a.w * b.w;
        #pragma unroll
        for (int off = 16; off > 0; off >>= 1)
            p += __shfl_xor_sync(0xFFFFFFFFu, p, off);
        if (lane == 0) out[i] = p;
    }
}

// ---------------- launch ----------------
extern "C" void kernel_launch(void* const* d_in, const int* in_sizes, int n_in,
                              void* d_out, int out_size) {
    const float* movie_feats = (const float*)d_in[0];
    const float* user_init   = (const float*)d_in[1];
    const int*   edge_src    = (const int*)d_in[2];
    const int*   edge_dst    = (const int*)d_in[3];
    const int*   lbl_user    = (const int*)d_in[4];
    const int*   lbl_movie   = (const int*)d_in[5];
    const int wi = (n_in >= 21) ? 7 : 6;   // skip scalar n_users if present
    const float* Wm     = (const float*)d_in[wi + 0];
    const float* bm     = (const float*)d_in[wi + 1];
    const float* Wl1_um = (const float*)d_in[wi + 2];
    const float* bl1_um = (const float*)d_in[wi + 3];
    const float* Wr1_um = (const float*)d_in[wi + 4];
    const float* Wl1_mu = (const float*)d_in[wi + 5];
    const float* bl1_mu = (const float*)d_in[wi + 6];
    const float* Wr1_mu = (const float*)d_in[wi + 7];
    const float* Wl2_um = (const float*)d_in[wi + 8];
    const float* bl2_um = (const float*)d_in[wi + 9];
    const float* Wr2_um = (const float*)d_in[wi + 10];
    const float* Wl2_mu = (const float*)d_in[wi + 11];
    const float* bl2_mu = (const float*)d_in[wi + 12];
    const float* Wr2_mu = (const float*)d_in[wi + 13];
    float* out = (float*)d_out;

    float *movie_x, *movie_h, *user_h, *aggU1, *aggU2, *aggM2, *movie_o, *user_o, *vecs;
    int *deg_u, *deg_m, *offU, *offM, *curU, *curM, *csrU, *csrM;
    cudaGetSymbolAddress((void**)&movie_x, g_movie_x);
    cudaGetSymbolAddress((void**)&movie_h, g_movie_h);
    cudaGetSymbolAddress((void**)&user_h,  g_user_h);
    cudaGetSymbolAddress((void**)&aggU1,   g_aggU1);
    cudaGetSymbolAddress((void**)&aggU2,   g_aggU2);
    cudaGetSymbolAddress((void**)&aggM2,   g_aggM2);
    cudaGetSymbolAddress((void**)&movie_o, g_movie_o);
    cudaGetSymbolAddress((void**)&user_o,  g_user_o);
    cudaGetSymbolAddress((void**)&vecs,    g_vecs);
    cudaGetSymbolAddress((void**)&deg_u,   g_deg_u);
    cudaGetSymbolAddress((void**)&deg_m,   g_deg_m);
    cudaGetSymbolAddress((void**)&offU,    g_offU);
    cudaGetSymbolAddress((void**)&offM,    g_offM);
    cudaGetSymbolAddress((void**)&curU,    g_curU);
    cudaGetSymbolAddress((void**)&curM,    g_curM);
    cudaGetSymbolAddress((void**)&csrU,    g_csrU);
    cudaGetSymbolAddress((void**)&csrM,    g_csrM);

    // 1) degrees
    zero_i_kernel<<<256, 256>>>(deg_u, cNU);
    zero_i_kernel<<<128, 256>>>(deg_m, cNM);
    deg_kernel<<<2048, 256>>>(edge_src, edge_dst, deg_u, deg_m, cE);

    // 2) CSR build
    scan_kernel<<<2, 1024>>>(deg_u, offU, curU, deg_m, offM, curM);
    scatter_kernel<<<2048, 256>>>(edge_src, edge_dst, curU, curM, csrU, csrM, cE);

    // 3) tiny precomputed vectors
    vec_kernel<<<1, 128>>>(user_init, Wl1_um, Wr1_mu, bl1_mu, vecs);

    // 4) movie_x = movie_feats @ Wm + bm
    gemm128_kernel<false, false><<<(cNM + 127) / 128, 256>>>(
        movie_feats, nullptr, Wm, nullptr, movie_x, bm, nullptr, nullptr, cNM, cFD / BK, 0);

    // 5) movie_h = relu(movie_x @ Wr1_um + bl1_um + (deg_m>0)*vsel)
    gemm128_kernel<true, true><<<(cNM + 127) / 128, 256>>>(
        movie_x, nullptr, Wr1_um, nullptr, movie_h, bl1_um, vecs, deg_m, cNM, cH / BK, 0);

    // 6) fused user-side aggregation (means of movie_x and movie_h)
    agg_user_kernel<<<4736, 256>>>(offU, csrU, movie_x, movie_h, aggU1, aggU2, cNU);

    // 7) user_h = relu(aggU1 @ Wl1_mu + cb1)
    gemm128_kernel<false, true><<<(cNU + 127) / 128, 256>>>(
        aggU1, nullptr, Wl1_mu, nullptr, user_h, vecs + cH, nullptr, nullptr, cNU, cH / BK, 0);

    // 8) movie-side aggregation (mean of user_h)
    agg_movie_kernel<<<4736, 256>>>(offM, csrM, user_h, aggM2, cNM);

    // 9) movie_o = aggM2 @ Wl2_um + bl2_um + movie_h @ Wr2_um
    gemm128_kernel<false, false><<<(cNM + 127) / 128, 256>>>(
        aggM2, movie_h, Wl2_um, Wr2_um, movie_o, bl2_um, nullptr, nullptr, cNM, cH / BK, cH / BK);

    // 10) user_o = aggU2 @ Wl2_mu + bl2_mu + user_h @ Wr2_mu
    gemm128_kernel<false, false><<<(cNU + 127) / 128, 256>>>(
        aggU2, user_h, Wl2_mu, Wr2_mu, user_o, bl2_mu, nullptr, nullptr, cNU, cH / BK, cH / BK);

    // 11) final dot products
    dot_kernel<<<4736, 256>>>(lbl_user, lbl_movie, user_o, movie_o, out, cEL);

    (void)in_sizes; (void)out_size;
}

// round 3
// speedup vs baseline: 2.5243x; 1.8343x over previous
#include <cuda_runtime.h>
#include <cuda_bf16.h>
#include <cstddef>
#include <cstdint>

// Problem constants
#define cH   128
#define cNU  200000
#define cNM  80000
#define cE   2000000
#define cEL  500000
#define cFD  512

#define TILE 1024
#define TU   ((cNU + TILE - 1) / TILE)   // 196
#define TM   ((cNM + TILE - 1) / TILE)   // 79

// ---------------- scratch (device globals) ----------------
__device__ float g_movie_x[(size_t)cNM * cH];
__device__ float g_movie_h[(size_t)cNM * cH];
__device__ float g_user_h [(size_t)cNU * cH];
__device__ float g_aggU1 [(size_t)cNU * cH];
__device__ float g_aggU2 [(size_t)cNU * cH];
__device__ float g_aggM2 [(size_t)cNM * cH];
__device__ float g_movie_o[(size_t)cNM * cH];
__device__ float g_user_o [(size_t)cNU * cH];
__device__ int   g_deg_u[cNU];
__device__ int   g_deg_m[cNM];
__device__ int   g_offU[cNU + 1];
__device__ int   g_offM[cNM + 1];
__device__ int   g_curU[cNU];
__device__ int   g_curM[cNM];
__device__ int   g_csrU[cE];
__device__ int   g_csrM[cE];
__device__ int   g_partU[TU];
__device__ int   g_partM[TM];
__device__ float g_vecs[2 * cH];

// ---------------- small utility kernels ----------------
__global__ void zero_i_kernel(int* p, int n) {
    int i = blockIdx.x * blockDim.x + threadIdx.x;
    int stride = gridDim.x * blockDim.x;
    for (; i < n; i += stride) p[i] = 0;
}

__global__ void deg_kernel(const int* __restrict__ src, const int* __restrict__ dst,
                           int* __restrict__ du, int* __restrict__ dm, int E) {
    int i = blockIdx.x * blockDim.x + threadIdx.x;
    int stride = gridDim.x * blockDim.x;
    for (; i < E; i += stride) {
        atomicAdd(&du[src[i]], 1);
        atomicAdd(&dm[dst[i]], 1);
    }
}

// ---- parallel scan, phase 1: per-tile partial sums
__global__ void partial_kernel(const int* __restrict__ degU, const int* __restrict__ degM,
                               int* __restrict__ partU, int* __restrict__ partM) {
    int b = blockIdx.x;
    const int* deg; int* part; int n, tile;
    if (b < TU) { deg = degU; part = partU; n = cNU; tile = b; }
    else        { deg = degM; part = partM; n = cNM; tile = b - TU; }

    int tid = threadIdx.x;
    int base = tile * TILE + tid * 4;
    int s = 0;
    #pragma unroll
    for (int j = 0; j < 4; j++) {
        int i = base + j;
        if (i < n) s += deg[i];
    }
    __shared__ int wsum[8];
    int lane = tid & 31, wid = tid >> 5;
    #pragma unroll
    for (int o = 16; o > 0; o >>= 1) s += __shfl_down_sync(0xffffffffu, s, o);
    if (lane == 0) wsum[wid] = s;
    __syncthreads();
    if (tid == 0) {
        int t = 0;
        #pragma unroll
        for (int w = 0; w < 8; w++) t += wsum[w];
        part[tile] = t;
    }
}

// ---- phase 2: scan the (small) partial arrays in-place -> exclusive tile bases
__global__ void scanpart_kernel(int* __restrict__ partU, int* __restrict__ partM) {
    int* part = (blockIdx.x == 0) ? partU : partM;
    int cnt   = (blockIdx.x == 0) ? TU : TM;
    int tid = threadIdx.x, lane = tid & 31, wid = tid >> 5;
    __shared__ int wsum[8];
    int v = (tid < cnt) ? part[tid] : 0;
    int x = v;
    #pragma unroll
    for (int o = 1; o < 32; o <<= 1) {
        int t = __shfl_up_sync(0xffffffffu, x, o);
        if (lane >= o) x += t;
    }
    if (lane == 31) wsum[wid] = x;
    __syncthreads();
    if (wid == 0) {
        int s = (lane < 8) ? wsum[lane] : 0;
        #pragma unroll
        for (int o = 1; o < 8; o <<= 1) {
            int t = __shfl_up_sync(0xffffffffu, s, o);
            if (lane >= o) s += t;
        }
        if (lane < 8) wsum[lane] = s;
    }
    __syncthreads();
    int incl = x + ((wid > 0) ? wsum[wid - 1] : 0);
    if (tid < cnt) part[tid] = incl - v;   // exclusive
}

// ---- phase 3: per-tile rescan + add base, write off & cur
__global__ void phase3_kernel(const int* __restrict__ degU, const int* __restrict__ degM,
                              const int* __restrict__ partU, const int* __restrict__ partM,
                              int* __restrict__ offU, int* __restrict__ curU,
                              int* __restrict__ offM, int* __restrict__ curM) {
    int b = blockIdx.x;
    const int* deg; const int* part; int* off; int* cur; int n, tile;
    if (b < TU) { deg = degU; part = partU; off = offU; cur = curU; n = cNU; tile = b; }
    else        { deg = degM; part = partM; off = offM; cur = curM; n = cNM; tile = b - TU; }

    int tid = threadIdx.x, lane = tid & 31, wid = tid >> 5;
    if (b == 0 && tid == 0) { offU[cNU] = cE; offM[cNM] = cE; }

    int base = tile * TILE + tid * 4;
    int v[4];
    int s = 0;
    #pragma unroll
    for (int j = 0; j < 4; j++) {
        int i = base + j;
        v[j] = (i < n) ? deg[i] : 0;
        s += v[j];
    }
    // exclusive block scan of thread sums
    __shared__ int wsum[8];
    int x = s;
    #pragma unroll
    for (int o = 1; o < 32; o <<= 1) {
        int t = __shfl_up_sync(0xffffffffu, x, o);
        if (lane >= o) x += t;
    }
    if (lane == 31) wsum[wid] = x;
    __syncthreads();
    if (wid == 0) {
        int t = (lane < 8) ? wsum[lane] : 0;
        #pragma unroll
        for (int o = 1; o < 8; o <<= 1) {
            int u = __shfl_up_sync(0xffffffffu, t, o);
            if (lane >= o) t += u;
        }
        if (lane < 8) wsum[lane] = t;
    }
    __syncthreads();
    int excl = x - s + ((wid > 0) ? wsum[wid - 1] : 0);
    int run = part[tile] + excl;
    #pragma unroll
    for (int j = 0; j < 4; j++) {
        int i = base + j;
        if (i < n) { off[i] = run; cur[i] = run; run += v[j]; }
    }
}

__global__ void scatter_kernel(const int* __restrict__ src, const int* __restrict__ dst,
                               int* __restrict__ curU, int* __restrict__ curM,
                               int* __restrict__ csrU, int* __restrict__ csrM, int E) {
    int i = blockIdx.x * blockDim.x + threadIdx.x;
    int stride = gridDim.x * blockDim.x;
    for (; i < E; i += stride) {
        int s = src[i];
        int d = dst[i];
        int p = atomicAdd(&curU[s], 1);
        csrU[p] = d;
        int q = atomicAdd(&curM[d], 1);
        csrM[q] = s;
    }
}

// vsel = user_init @ Wl1_um ; cb1 = bl1_mu + user_init @ Wr1_mu   (exact fp32)
__global__ void vec_kernel(const float* __restrict__ user_init,
                           const float* __restrict__ Wl1_um,
                           const float* __restrict__ Wr1_mu,
                           const float* __restrict__ bl1_mu,
                           float* __restrict__ vecs) {
    int j = threadIdx.x;
    if (j >= cH) return;
    float s1 = 0.f, s2 = 0.f;
    for (int k = 0; k < cH; k++) {
        float u = user_init[k];
        s1 = fmaf(u, Wl1_um[k * cH + j], s1);
        s2 = fmaf(u, Wr1_mu[k * cH + j], s2);
    }
    vecs[j]      = s1;
    vecs[cH + j] = bl1_mu[j] + s2;
}

// ---------------- CSR gather aggregations ----------------
__global__ void agg_user_kernel(const int* __restrict__ off, const int* __restrict__ csr,
                                const float* __restrict__ mx, const float* __restrict__ mh,
                                float* __restrict__ aU1, float* __restrict__ aU2, int NU) {
    int w    = (blockIdx.x * blockDim.x + threadIdx.x) >> 5;
    int lane = threadIdx.x & 31;
    int nw   = (gridDim.x * blockDim.x) >> 5;
    for (int u = w; u < NU; u += nw) {
        int s = off[u], e = off[u + 1];
        float4 a1 = make_float4(0.f, 0.f, 0.f, 0.f);
        float4 a2 = make_float4(0.f, 0.f, 0.f, 0.f);
        float4 a3 = make_float4(0.f, 0.f, 0.f, 0.f);
        float4 a4 = make_float4(0.f, 0.f, 0.f, 0.f);
        int i = s;
        for (; i + 1 < e; i += 2) {
            int d0 = csr[i];
            int d1 = csr[i + 1];
            float4 v0 = ((const float4*)(mx + (size_t)d0 * 128))[lane];
            float4 w0 = ((const float4*)(mh + (size_t)d0 * 128))[lane];
            float4 v1 = ((const float4*)(mx + (size_t)d1 * 128))[lane];
            float4 w1 = ((const float4*)(mh + (size_t)d1 * 128))[lane];
            a1.x += v0.x; a1.y += v0.y; a1.z += v0.z; a1.w += v0.w;
            a2.x += w0.x; a2.y += w0.y; a2.z += w0.z; a2.w += w0.w;
            a3.x += v1.x; a3.y += v1.y; a3.z += v1.z; a3.w += v1.w;
            a4.x += w1.x; a4.y += w1.y; a4.z += w1.z; a4.w += w1.w;
        }
        if (i < e) {
            int d0 = csr[i];
            float4 v0 = ((const float4*)(mx + (size_t)d0 * 128))[lane];
            float4 w0 = ((const float4*)(mh + (size_t)d0 * 128))[lane];
            a1.x += v0.x; a1.y += v0.y; a1.z += v0.z; a1.w += v0.w;
            a2.x += w0.x; a2.y += w0.y; a2.z += w0.z; a2.w += w0.w;
        }
        float sc = (e > s) ? 1.f / (float)(e - s) : 0.f;
        float4 o1 = make_float4((a1.x + a3.x) * sc, (a1.y + a3.y) * sc, (a1.z + a3.z) * sc, (a1.w + a3.w) * sc);
        float4 o2 = make_float4((a2.x + a4.x) * sc, (a2.y + a4.y) * sc, (a2.z + a4.z) * sc, (a2.w + a4.w) * sc);
        ((float4*)(aU1 + (size_t)u * 128))[lane] = o1;
        ((float4*)(aU2 + (size_t)u * 128))[lane] = o2;
    }
}

__global__ void agg_movie_kernel(const int* __restrict__ off, const int* __restrict__ csr,
                                 const float* __restrict__ uh,
                                 float* __restrict__ aM2, int NM) {
    int w    = (blockIdx.x * blockDim.x + threadIdx.x) >> 5;
    int lane = threadIdx.x & 31;
    int nw   = (gridDim.x * blockDim.x) >> 5;
    for (int m = w; m < NM; m += nw) {
        int s = off[m], e = off[m + 1];
        float4 a1 = make_float4(0.f, 0.f, 0.f, 0.f);
        float4 a2 = make_float4(0.f, 0.f, 0.f, 0.f);
        int i = s;
        for (; i + 1 < e; i += 2) {
            int d0 = csr[i];
            int d1 = csr[i + 1];
            float4 v0 = ((const float4*)(uh + (size_t)d0 * 128))[lane];
            float4 v1 = ((const float4*)(uh + (size_t)d1 * 128))[lane];
            a1.x += v0.x; a1.y += v0.y; a1.z += v0.z; a1.w += v0.w;
            a2.x += v1.x; a2.y += v1.y; a2.z += v1.z; a2.w += v1.w;
        }
        if (i < e) {
            int d0 = csr[i];
            float4 v0 = ((const float4*)(uh + (size_t)d0 * 128))[lane];
            a1.x += v0.x; a1.y += v0.y; a1.z += v0.z; a1.w += v0.w;
        }
        float sc = (e > s) ? 1.f / (float)(e - s) : 0.f;
        float4 o = make_float4((a1.x + a2.x) * sc, (a1.y + a2.y) * sc, (a1.z + a2.z) * sc, (a1.w + a2.w) * sc);
        ((float4*)(aM2 + (size_t)m * 128))[lane] = o;
    }
}

// ---------------- tensor-core SGEMM via split-bf16 (3-pass) ----------------
#define BK   16
#define ASTR 24
#define BSTR 136

__device__ __forceinline__ unsigned pack_bf16(__nv_bfloat16 a, __nv_bfloat16 b) {
    __nv_bfloat162 t = __halves2bfloat162(a, b);
    return reinterpret_cast<unsigned&>(t);
}
__device__ __forceinline__ void split_f32(float x, __nv_bfloat16& h, __nv_bfloat16& l) {
    h = __float2bfloat16(x);
    l = __float2bfloat16(x - __bfloat162float(h));
}
__device__ __forceinline__ void ldsm_x4(uint32_t* r, uint32_t addr) {
    asm volatile("ldmatrix.sync.aligned.m8n8.x4.shared.b16 {%0,%1,%2,%3}, [%4];"
                 : "=r"(r[0]), "=r"(r[1]), "=r"(r[2]), "=r"(r[3]) : "r"(addr));
}
__device__ __forceinline__ void ldsm_x4_t(uint32_t* r, uint32_t addr) {
    asm volatile("ldmatrix.sync.aligned.m8n8.x4.trans.shared.b16 {%0,%1,%2,%3}, [%4];"
                 : "=r"(r[0]), "=r"(r[1]), "=r"(r[2]), "=r"(r[3]) : "r"(addr));
}
__device__ __forceinline__ void mma_bf16(float* d, const uint32_t* a, const uint32_t* b) {
    asm volatile("mma.sync.aligned.m16n8k16.row.col.f32.bf16.bf16.f32 "
                 "{%0,%1,%2,%3}, {%4,%5,%6,%7}, {%8,%9}, {%0,%1,%2,%3};"
                 : "+f"(d[0]), "+f"(d[1]), "+f"(d[2]), "+f"(d[3])
                 : "r"(a[0]), "r"(a[1]), "r"(a[2]), "r"(a[3]), "r"(b[0]), "r"(b[1]));
}

template<bool BIAS_SEL, bool RELU>
__global__ void __launch_bounds__(256)
gemm128_kernel(const float* __restrict__ A1, const float* __restrict__ A2,
               const float* __restrict__ B1, const float* __restrict__ B2,
               float* __restrict__ C,
               const float* __restrict__ bias,
               const float* __restrict__ vsel,
               const int*   __restrict__ deg,
               int M, int KT1, int KT2) {
    __shared__ __nv_bfloat16 Ah[2][128][ASTR];
    __shared__ __nv_bfloat16 Al[2][128][ASTR];
    __shared__ __nv_bfloat16 Bh[2][BK][BSTR];
    __shared__ __nv_bfloat16 Bl[2][BK][BSTR];
    __shared__ float sBias[128];
    __shared__ float sVsel[128];

    const int tid  = threadIdx.x;
    const int lane = tid & 31;
    const int wid  = tid >> 5;
    const int wm   = wid & 3;     // 4 warps over M (32 rows each)
    const int wn   = wid >> 2;    // 2 warps over N (64 cols each)
    const int m0   = blockIdx.x * 128;
    const int lda1 = KT1 * BK;
    const int lda2 = KT2 * BK;
    const int KT   = KT1 + KT2;

    if (tid < 128) {
        sBias[tid] = bias[tid];
        if (BIAS_SEL) sVsel[tid] = vsel[tid];
    }

    const int arow0 = tid >> 2;           // + 64 for second
    const int ac4   = (tid & 3) << 2;
    const int brow0 = tid >> 5;           // + 8 for second
    const int bn4   = (tid & 31) << 2;

    float4 rA[2], rB[2];

    auto loadTile = [&](int t) {
        const bool first = (t < KT1);
        #pragma unroll
        for (int i = 0; i < 2; i++) {
            int row = arow0 + i * 64;
            int m = m0 + row;
            float4 v = make_float4(0.f, 0.f, 0.f, 0.f);
            if (m < M) {
                const float* p = first ? (A1 + (size_t)m * lda1 + t * BK + ac4)
                                       : (A2 + (size_t)m * lda2 + (t - KT1) * BK + ac4);
                v = *(const float4*)p;
            }
            rA[i] = v;
        }
        #pragma unroll
        for (int i = 0; i < 2; i++) {
            int row = brow0 + i * 8;
            const float* p = first ? (B1 + (size_t)(t * BK + row) * 128 + bn4)
                                   : (B2 + (size_t)((t - KT1) * BK + row) * 128 + bn4);
            rB[i] = *(const float4*)p;
        }
    };
    auto storeTile = [&](int buf) {
        #pragma unroll
        for (int i = 0; i < 2; i++) {
            int row = arow0 + i * 64;
            const float* v = &rA[i].x;
            __nv_bfloat16 h[4], l[4];
            #pragma unroll
            for (int j = 0; j < 4; j++) split_f32(v[j], h[j], l[j]);
            uint2 ph = make_uint2(pack_bf16(h[0], h[1]), pack_bf16(h[2], h[3]));
            uint2 pl = make_uint2(pack_bf16(l[0], l[1]), pack_bf16(l[2], l[3]));
            *(uint2*)&Ah[buf][row][ac4] = ph;
            *(uint2*)&Al[buf][row][ac4] = pl;
        }
        #pragma unroll
        for (int i = 0; i < 2; i++) {
            int row = brow0 + i * 8;
            const float* v = &rB[i].x;
            __nv_bfloat16 h[4], l[4];
            #pragma unroll
            for (int j = 0; j < 4; j++) split_f32(v[j], h[j], l[j]);
            uint2 ph = make_uint2(pack_bf16(h[0], h[1]), pack_bf16(h[2], h[3]));
            uint2 pl = make_uint2(pack_bf16(l[0], l[1]), pack_bf16(l[2], l[3]));
            *(uint2*)&Bh[buf][row][bn4] = ph;
            *(uint2*)&Bl[buf][row][bn4] = pl;
        }
    };

    float d[2][8][4];
    #pragma unroll
    for (int mt = 0; mt < 2; mt++)
        #pragma unroll
        for (int nt = 0; nt < 8; nt++)
            #pragma unroll
            for (int j = 0; j < 4; j++) d[mt][nt][j] = 0.f;

    // ldmatrix lane coords
    const int ar = lane & 15;
    const int ac = (lane >> 4) << 3;
    const int br = lane & 15;
    const int bc = wn * 64 + ((lane >> 4) << 3);

    loadTile(0);
    storeTile(0);
    __syncthreads();

    for (int t = 0; t < KT; t++) {
        const int cb = t & 1;
        if (t + 1 < KT) loadTile(t + 1);

        uint32_t fah[2][4], fal[2][4];
        #pragma unroll
        for (int mt = 0; mt < 2; mt++) {
            int row = wm * 32 + mt * 16 + ar;
            ldsm_x4(fah[mt], (uint32_t)__cvta_generic_to_shared(&Ah[cb][row][ac]));
            ldsm_x4(fal[mt], (uint32_t)__cvta_generic_to_shared(&Al[cb][row][ac]));
        }
        #pragma unroll
        for (int ntp = 0; ntp < 4; ntp++) {
            uint32_t fbh[4], fbl[4];
            ldsm_x4_t(fbh, (uint32_t)__cvta_generic_to_shared(&Bh[cb][br][bc + ntp * 16]));
            ldsm_x4_t(fbl, (uint32_t)__cvta_generic_to_shared(&Bl[cb][br][bc + ntp * 16]));
            #pragma unroll
            for (int mt = 0; mt < 2; mt++) {
                mma_bf16(d[mt][2 * ntp],     fah[mt], fbh);
                mma_bf16(d[mt][2 * ntp],     fal[mt], fbh);
                mma_bf16(d[mt][2 * ntp],     fah[mt], fbl);
                mma_bf16(d[mt][2 * ntp + 1], fah[mt], fbh + 2);
                mma_bf16(d[mt][2 * ntp + 1], fal[mt], fbh + 2);
                mma_bf16(d[mt][2 * ntp + 1], fah[mt], fbl + 2);
            }
        }
        if (t + 1 < KT) storeTile((t + 1) & 1);
        __syncthreads();
    }

    // epilogue: d[mt][nt] regs {0,1}=row r cols c,c+1 ; {2,3}=row r+8
    const int rb  = m0 + wm * 32 + (lane >> 2);
    const int cb0 = wn * 64 + (lane & 3) * 2;
    #pragma unroll
    for (int mt = 0; mt < 2; mt++) {
        #pragma unroll
        for (int h = 0; h < 2; h++) {
            int m = rb + mt * 16 + h * 8;
            if (m >= M) continue;
            float sel = 0.f;
            if (BIAS_SEL) sel = (deg[m] > 0) ? 1.f : 0.f;
            #pragma unroll
            for (int nt = 0; nt < 8; nt++) {
                int col = cb0 + nt * 8;
                float x = d[mt][nt][h * 2 + 0] + sBias[col];
                float y = d[mt][nt][h * 2 + 1] + sBias[col + 1];
                if (BIAS_SEL) { x += sel * sVsel[col]; y += sel * sVsel[col + 1]; }
                if (RELU) { x = fmaxf(x, 0.f); y = fmaxf(y, 0.f); }
                *(float2*)&C[(size_t)m * 128 + col] = make_float2(x, y);
            }
        }
    }
}

// ---------------- final edge dot products ----------------
__global__ void dot_kernel(const int* __restrict__ lu, const int* __restrict__ lm,
                           const float* __restrict__ U, const float* __restrict__ Mo,
                           float* __restrict__ out, int EL) {
    int w    = (blockIdx.x * blockDim.x + threadIdx.x) >> 5;
    int lane = threadIdx.x & 31;
    int nw   = (gridDim.x * blockDim.x) >> 5;
    for (int i = w; i < EL; i += nw) {
        int u = lu[i];
        int m = lm[i];
        float4 a = ((const float4*)(U  + (size_t)u * 128))[lane];
        float4 b = ((const float4*)(Mo + (size_t)m * 128))[lane];
        float p = a.x * b.x + a.y * b.y + a.z * b.z + a.w * b.w;
        #pragma unroll
        for (int off = 16; off > 0; off >>= 1)
            p += __shfl_xor_sync(0xFFFFFFFFu, p, off);
        if (lane == 0) out[i] = p;
    }
}

// ---------------- launch ----------------
extern "C" void kernel_launch(void* const* d_in, const int* in_sizes, int n_in,
                              void* d_out, int out_size) {
    const float* movie_feats = (const float*)d_in[0];
    const float* user_init   = (const float*)d_in[1];
    const int*   edge_src    = (const int*)d_in[2];
    const int*   edge_dst    = (const int*)d_in[3];
    const int*   lbl_user    = (const int*)d_in[4];
    const int*   lbl_movie   = (const int*)d_in[5];
    const int wi = (n_in >= 21) ? 7 : 6;
    const float* Wm     = (const float*)d_in[wi + 0];
    const float* bm     = (const float*)d_in[wi + 1];
    const float* Wl1_um = (const float*)d_in[wi + 2];
    const float* bl1_um = (const float*)d_in[wi + 3];
    const float* Wr1_um = (const float*)d_in[wi + 4];
    const float* Wl1_mu = (const float*)d_in[wi + 5];
    const float* bl1_mu = (const float*)d_in[wi + 6];
    const float* Wr1_mu = (const float*)d_in[wi + 7];
    const float* Wl2_um = (const float*)d_in[wi + 8];
    const float* bl2_um = (const float*)d_in[wi + 9];
    const float* Wr2_um = (const float*)d_in[wi + 10];
    const float* Wl2_mu = (const float*)d_in[wi + 11];
    const float* bl2_mu = (const float*)d_in[wi + 12];
    const float* Wr2_mu = (const float*)d_in[wi + 13];
    float* out = (float*)d_out;

    float *movie_x, *movie_h, *user_h, *aggU1, *aggU2, *aggM2, *movie_o, *user_o, *vecs;
    int *deg_u, *deg_m, *offU, *offM, *curU, *curM, *csrU, *csrM, *partU, *partM;
    cudaGetSymbolAddress((void**)&movie_x, g_movie_x);
    cudaGetSymbolAddress((void**)&movie_h, g_movie_h);
    cudaGetSymbolAddress((void**)&user_h,  g_user_h);
    cudaGetSymbolAddress((void**)&aggU1,   g_aggU1);
    cudaGetSymbolAddress((void**)&aggU2,   g_aggU2);
    cudaGetSymbolAddress((void**)&aggM2,   g_aggM2);
    cudaGetSymbolAddress((void**)&movie_o, g_movie_o);
    cudaGetSymbolAddress((void**)&user_o,  g_user_o);
    cudaGetSymbolAddress((void**)&vecs,    g_vecs);
    cudaGetSymbolAddress((void**)&deg_u,   g_deg_u);
    cudaGetSymbolAddress((void**)&deg_m,   g_deg_m);
    cudaGetSymbolAddress((void**)&offU,    g_offU);
    cudaGetSymbolAddress((void**)&offM,    g_offM);
    cudaGetSymbolAddress((void**)&curU,    g_curU);
    cudaGetSymbolAddress((void**)&curM,    g_curM);
    cudaGetSymbolAddress((void**)&csrU,    g_csrU);
    cudaGetSymbolAddress((void**)&csrM,    g_csrM);
    cudaGetSymbolAddress((void**)&partU,   g_partU);
    cudaGetSymbolAddress((void**)&partM,   g_partM);

    // 1) degrees
    zero_i_kernel<<<256, 256>>>(deg_u, cNU);
    zero_i_kernel<<<128, 256>>>(deg_m, cNM);
    deg_kernel<<<2048, 256>>>(edge_src, edge_dst, deg_u, deg_m, cE);

    // 2) CSR offsets (parallel 3-phase scan) + scatter
    partial_kernel<<<TU + TM, 256>>>(deg_u, deg_m, partU, partM);
    scanpart_kernel<<<2, 256>>>(partU, partM);
    phase3_kernel<<<TU + TM, 256>>>(deg_u, deg_m, partU, partM, offU, curU, offM, curM);
    scatter_kernel<<<2048, 256>>>(edge_src, edge_dst, curU, curM, csrU, csrM, cE);

    // 3) tiny precomputed vectors
    vec_kernel<<<1, 128>>>(user_init, Wl1_um, Wr1_mu, bl1_mu, vecs);

    // 4) movie_x = movie_feats @ Wm + bm
    gemm128_kernel<false, false><<<(cNM + 127) / 128, 256>>>(
        movie_feats, nullptr, Wm, nullptr, movie_x, bm, nullptr, nullptr, cNM, cFD / BK, 0);

    // 5) movie_h = relu(movie_x @ Wr1_um + bl1_um + (deg_m>0)*vsel)
    gemm128_kernel<true, true><<<(cNM + 127) / 128, 256>>>(
        movie_x, nullptr, Wr1_um, nullptr, movie_h, bl1_um, vecs, deg_m, cNM, cH / BK, 0);

    // 6) fused user-side aggregation
    agg_user_kernel<<<4736, 256>>>(offU, csrU, movie_x, movie_h, aggU1, aggU2, cNU);

    // 7) user_h = relu(aggU1 @ Wl1_mu + cb1)
    gemm128_kernel<false, true><<<(cNU + 127) / 128, 256>>>(
        aggU1, nullptr, Wl1_mu, nullptr, user_h, vecs + cH, nullptr, nullptr, cNU, cH / BK, 0);

    // 8) movie-side aggregation
    agg_movie_kernel<<<4736, 256>>>(offM, csrM, user_h, aggM2, cNM);

    // 9) movie_o = aggM2 @ Wl2_um + bl2_um + movie_h @ Wr2_um
    gemm128_kernel<false, false><<<(cNM + 127) / 128, 256>>>(
        aggM2, movie_h, Wl2_um, Wr2_um, movie_o, bl2_um, nullptr, nullptr, cNM, cH / BK, cH / BK);

    // 10) user_o = aggU2 @ Wl2_mu + bl2_mu + user_h @ Wr2_mu
    gemm128_kernel<false, false><<<(cNU + 127) / 128, 256>>>(
        aggU2, user_h, Wl2_mu, Wr2_mu, user_o, bl2_mu, nullptr, nullptr, cNU, cH / BK, cH / BK);

    // 11) final dot products
    dot_kernel<<<4736, 256>>>(lbl_user, lbl_movie, user_o, movie_o, out, cEL);

    (void)in_sizes; (void)out_size;
}

// round 5
// speedup vs baseline: 2.6066x; 1.0326x over previous
#include <cuda_runtime.h>
#include <cuda_bf16.h>
#include <cstddef>
#include <cstdint>

// Problem constants
#define cH   128
#define cNU  200000
#define cNM  80000
#define cE   2000000
#define cEL  500000
#define cFD  512

#define TILE 1024
#define TU   ((cNU + TILE - 1) / TILE)   // 196
#define TM   ((cNM + TILE - 1) / TILE)   // 79

// ---------------- scratch (device globals) ----------------
__device__ float g_movie_x[(size_t)cNM * cH];
__device__ float g_movie_h[(size_t)cNM * cH];
__device__ float g_user_h [(size_t)cNU * cH];
__device__ float g_aggU1 [(size_t)cNU * cH];
__device__ float g_aggU2 [(size_t)cNU * cH];
__device__ float g_aggM2 [(size_t)cNM * cH];
__device__ float g_movie_o[(size_t)cNM * cH];
__device__ float g_user_o [(size_t)cNU * cH];
__device__ int   g_deg_u[cNU];
__device__ int   g_deg_m[cNM];
__device__ int   g_offU[cNU + 1];
__device__ int   g_offM[cNM + 1];
__device__ int   g_curU[cNU];
__device__ int   g_curM[cNM];
__device__ int   g_csrU[cE];
__device__ int   g_csrM[cE];
__device__ int   g_partU[TU];
__device__ int   g_partM[TM];
__device__ float g_vecs[2 * cH];

// ---------------- small utility kernels ----------------
__global__ void zero_i_kernel(int* p, int n) {
    int i = blockIdx.x * blockDim.x + threadIdx.x;
    int stride = gridDim.x * blockDim.x;
    for (; i < n; i += stride) p[i] = 0;
}

// ---- device bodies (callable from fused kernels) ----
__device__ __forceinline__ void deg_body(const int* __restrict__ src, const int* __restrict__ dst,
                                         int* __restrict__ du, int* __restrict__ dm,
                                         int E, int vbid, int vgrid) {
    int i = vbid * 256 + threadIdx.x;
    int stride = vgrid * 256;
    for (; i < E; i += stride) {
        atomicAdd(&du[src[i]], 1);
        atomicAdd(&dm[dst[i]], 1);
    }
}

__device__ __forceinline__ void scatter_body(const int* __restrict__ src, const int* __restrict__ dst,
                                             int* __restrict__ curU, int* __restrict__ curM,
                                             int* __restrict__ csrU, int* __restrict__ csrM,
                                             int E, int vbid, int vgrid) {
    int i = vbid * 256 + threadIdx.x;
    int stride = vgrid * 256;
    for (; i < E; i += stride) {
        int s = src[i];
        int d = dst[i];
        int p = atomicAdd(&curU[s], 1);
        csrU[p] = d;
        int q = atomicAdd(&curM[d], 1);
        csrM[q] = s;
    }
}

__device__ __forceinline__ void vec_body(const float* __restrict__ user_init,
                                         const float* __restrict__ Wl1_um,
                                         const float* __restrict__ Wr1_mu,
                                         const float* __restrict__ bl1_mu,
                                         float* __restrict__ vecs) {
    int j = threadIdx.x;
    if (j >= cH) return;
    float s1 = 0.f, s2 = 0.f;
    for (int k = 0; k < cH; k++) {
        float u = user_init[k];
        s1 = fmaf(u, Wl1_um[k * cH + j], s1);
        s2 = fmaf(u, Wr1_mu[k * cH + j], s2);
    }
    vecs[j]      = s1;
    vecs[cH + j] = bl1_mu[j] + s2;
}

// fp32 movie-side aggregation body
__device__ __forceinline__ void agg_movie_body(const int* __restrict__ off, const int* __restrict__ csr,
                                               const float* __restrict__ uh,
                                               float* __restrict__ aM2, int NM, int vbid, int vgrid) {
    int w    = vbid * 8 + (threadIdx.x >> 5);
    int lane = threadIdx.x & 31;
    int nw   = vgrid * 8;
    for (int m = w; m < NM; m += nw) {
        int s = off[m], e = off[m + 1];
        float4 a1 = make_float4(0.f, 0.f, 0.f, 0.f);
        float4 a2 = make_float4(0.f, 0.f, 0.f, 0.f);
        int i = s;
        for (; i + 1 < e; i += 2) {
            int d0 = csr[i];
            int d1 = csr[i + 1];
            float4 v0 = ((const float4*)(uh + (size_t)d0 * 128))[lane];
            float4 v1 = ((const float4*)(uh + (size_t)d1 * 128))[lane];
            a1.x += v0.x; a1.y += v0.y; a1.z += v0.z; a1.w += v0.w;
            a2.x += v1.x; a2.y += v1.y; a2.z += v1.z; a2.w += v1.w;
        }
        if (i < e) {
            int d0 = csr[i];
            float4 v0 = ((const float4*)(uh + (size_t)d0 * 128))[lane];
            a1.x += v0.x; a1.y += v0.y; a1.z += v0.z; a1.w += v0.w;
        }
        float sc = (e > s) ? 1.f / (float)(e - s) : 0.f;
        float4 o = make_float4((a1.x + a2.x) * sc, (a1.y + a2.y) * sc, (a1.z + a2.z) * sc, (a1.w + a2.w) * sc);
        ((float4*)(aM2 + (size_t)m * 128))[lane] = o;
    }
}

// ---- parallel scan ----
__global__ void partial_kernel(const int* __restrict__ degU, const int* __restrict__ degM,
                               int* __restrict__ partU, int* __restrict__ partM) {
    int b = blockIdx.x;
    const int* deg; int* part; int n, tile;
    if (b < TU) { deg = degU; part = partU; n = cNU; tile = b; }
    else        { deg = degM; part = partM; n = cNM; tile = b - TU; }

    int tid = threadIdx.x;
    int base = tile * TILE + tid * 4;
    int s = 0;
    #pragma unroll
    for (int j = 0; j < 4; j++) {
        int i = base + j;
        if (i < n) s += deg[i];
    }
    __shared__ int wsum[8];
    int lane = tid & 31, wid = tid >> 5;
    #pragma unroll
    for (int o = 16; o > 0; o >>= 1) s += __shfl_down_sync(0xffffffffu, s, o);
    if (lane == 0) wsum[wid] = s;
    __syncthreads();
    if (tid == 0) {
        int t = 0;
        #pragma unroll
        for (int w = 0; w < 8; w++) t += wsum[w];
        part[tile] = t;
    }
}

__global__ void scanpart_kernel(int* __restrict__ partU, int* __restrict__ partM) {
    int* part = (blockIdx.x == 0) ? partU : partM;
    int cnt   = (blockIdx.x == 0) ? TU : TM;
    int tid = threadIdx.x, lane = tid & 31, wid = tid >> 5;
    __shared__ int wsum[8];
    int v = (tid < cnt) ? part[tid] : 0;
    int x = v;
    #pragma unroll
    for (int o = 1; o < 32; o <<= 1) {
        int t = __shfl_up_sync(0xffffffffu, x, o);
        if (lane >= o) x += t;
    }
    if (lane == 31) wsum[wid] = x;
    __syncthreads();
    if (wid == 0) {
        int s = (lane < 8) ? wsum[lane] : 0;
        #pragma unroll
        for (int o = 1; o < 8; o <<= 1) {
            int t = __shfl_up_sync(0xffffffffu, s, o);
            if (lane >= o) s += t;
        }
        if (lane < 8) wsum[lane] = s;
    }
    __syncthreads();
    int incl = x + ((wid > 0) ? wsum[wid - 1] : 0);
    if (tid < cnt) part[tid] = incl - v;
}

__global__ void phase3_kernel(const int* __restrict__ degU, const int* __restrict__ degM,
                              const int* __restrict__ partU, const int* __restrict__ partM,
                              int* __restrict__ offU, int* __restrict__ curU,
                              int* __restrict__ offM, int* __restrict__ curM) {
    int b = blockIdx.x;
    const int* deg; const int* part; int* off; int* cur; int n, tile;
    if (b < TU) { deg = degU; part = partU; off = offU; cur = curU; n = cNU; tile = b; }
    else        { deg = degM; part = partM; off = offM; cur = curM; n = cNM; tile = b - TU; }

    int tid = threadIdx.x, lane = tid & 31, wid = tid >> 5;
    if (b == 0 && tid == 0) { offU[cNU] = cE; offM[cNM] = cE; }

    int base = tile * TILE + tid * 4;
    int v[4];
    int s = 0;
    #pragma unroll
    for (int j = 0; j < 4; j++) {
        int i = base + j;
        v[j] = (i < n) ? deg[i] : 0;
        s += v[j];
    }
    __shared__ int wsum[8];
    int x = s;
    #pragma unroll
    for (int o = 1; o < 32; o <<= 1) {
        int t = __shfl_up_sync(0xffffffffu, x, o);
        if (lane >= o) x += t;
    }
    if (lane == 31) wsum[wid] = x;
    __syncthreads();
    if (wid == 0) {
        int t = (lane < 8) ? wsum[lane] : 0;
        #pragma unroll
        for (int o = 1; o < 8; o <<= 1) {
            int u = __shfl_up_sync(0xffffffffu, t, o);
            if (lane >= o) t += u;
        }
        if (lane < 8) wsum[lane] = t;
    }
    __syncthreads();
    int excl = x - s + ((wid > 0) ? wsum[wid - 1] : 0);
    int run = part[tile] + excl;
    #pragma unroll
    for (int j = 0; j < 4; j++) {
        int i = base + j;
        if (i < n) { off[i] = run; cur[i] = run; run += v[j]; }
    }
}

// ---------------- fused user-side aggregation (fp32 gathers) ----------------
__global__ void agg_user_kernel(const int* __restrict__ off, const int* __restrict__ csr,
                                const float* __restrict__ mx, const float* __restrict__ mh,
                                float* __restrict__ aU1, float* __restrict__ aU2, int NU) {
    int w    = (blockIdx.x * blockDim.x + threadIdx.x) >> 5;
    int lane = threadIdx.x & 31;
    int nw   = (gridDim.x * blockDim.x) >> 5;
    for (int u = w; u < NU; u += nw) {
        int s = off[u], e = off[u + 1];
        float4 a1 = make_float4(0.f, 0.f, 0.f, 0.f);
        float4 a2 = make_float4(0.f, 0.f, 0.f, 0.f);
        float4 a3 = make_float4(0.f, 0.f, 0.f, 0.f);
        float4 a4 = make_float4(0.f, 0.f, 0.f, 0.f);
        int i = s;
        for (; i + 1 < e; i += 2) {
            int d0 = csr[i];
            int d1 = csr[i + 1];
            float4 v0 = ((const float4*)(mx + (size_t)d0 * 128))[lane];
            float4 w0 = ((const float4*)(mh + (size_t)d0 * 128))[lane];
            float4 v1 = ((const float4*)(mx + (size_t)d1 * 128))[lane];
            float4 w1 = ((const float4*)(mh + (size_t)d1 * 128))[lane];
            a1.x += v0.x; a1.y += v0.y; a1.z += v0.z; a1.w += v0.w;
            a2.x += w0.x; a2.y += w0.y; a2.z += w0.z; a2.w += w0.w;
            a3.x += v1.x; a3.y += v1.y; a3.z += v1.z; a3.w += v1.w;
            a4.x += w1.x; a4.y += w1.y; a4.z += w1.z; a4.w += w1.w;
        }
        if (i < e) {
            int d0 = csr[i];
            float4 v0 = ((const float4*)(mx + (size_t)d0 * 128))[lane];
            float4 w0 = ((const float4*)(mh + (size_t)d0 * 128))[lane];
            a1.x += v0.x; a1.y += v0.y; a1.z += v0.z; a1.w += v0.w;
            a2.x += w0.x; a2.y += w0.y; a2.z += w0.z; a2.w += w0.w;
        }
        float sc = (e > s) ? 1.f / (float)(e - s) : 0.f;
        float4 o1 = make_float4((a1.x + a3.x) * sc, (a1.y + a3.y) * sc, (a1.z + a3.z) * sc, (a1.w + a3.w) * sc);
        float4 o2 = make_float4((a2.x + a4.x) * sc, (a2.y + a4.y) * sc, (a2.z + a4.z) * sc, (a2.w + a4.w) * sc);
        ((float4*)(aU1 + (size_t)u * 128))[lane] = o1;
        ((float4*)(aU2 + (size_t)u * 128))[lane] = o2;
    }
}

// ---------------- tensor-core SGEMM via split-bf16 ----------------
#define BK   16
#define ASTR 24
#define BSTR 136

__device__ __forceinline__ unsigned pack_bf16(__nv_bfloat16 a, __nv_bfloat16 b) {
    __nv_bfloat162 t = __halves2bfloat162(a, b);
    return reinterpret_cast<unsigned&>(t);
}
__device__ __forceinline__ void split_f32(float x, __nv_bfloat16& h, __nv_bfloat16& l) {
    h = __float2bfloat16(x);
    l = __float2bfloat16(x - __bfloat162float(h));
}
__device__ __forceinline__ void ldsm_x4(uint32_t* r, uint32_t addr) {
    asm volatile("ldmatrix.sync.aligned.m8n8.x4.shared.b16 {%0,%1,%2,%3}, [%4];"
                 : "=r"(r[0]), "=r"(r[1]), "=r"(r[2]), "=r"(r[3]) : "r"(addr));
}
__device__ __forceinline__ void ldsm_x4_t(uint32_t* r, uint32_t addr) {
    asm volatile("ldmatrix.sync.aligned.m8n8.x4.trans.shared.b16 {%0,%1,%2,%3}, [%4];"
                 : "=r"(r[0]), "=r"(r[1]), "=r"(r[2]), "=r"(r[3]) : "r"(addr));
}
__device__ __forceinline__ void mma_bf16(float* d, const uint32_t* a, const uint32_t* b) {
    asm volatile("mma.sync.aligned.m16n8k16.row.col.f32.bf16.bf16.f32 "
                 "{%0,%1,%2,%3}, {%4,%5,%6,%7}, {%8,%9}, {%0,%1,%2,%3};"
                 : "+f"(d[0]), "+f"(d[1]), "+f"(d[2]), "+f"(d[3])
                 : "r"(a[0]), "r"(a[1]), "r"(a[2]), "r"(a[3]), "r"(b[0]), "r"(b[1]));
}

template<bool BIAS_SEL, bool RELU>
__device__ __forceinline__ void gemm128_body(
    const float* __restrict__ A1, const float* __restrict__ A2,
    const float* __restrict__ B1, const float* __restrict__ B2,
    float* __restrict__ C,
    const float* __restrict__ bias, const float* __restrict__ vsel,
    const int* __restrict__ deg,
    int M, int KT1, int KT2, int bid) {
    __shared__ __nv_bfloat16 Ah[2][128][ASTR];
    __shared__ __nv_bfloat16 Al[2][128][ASTR];
    __shared__ __nv_bfloat16 Bh[2][BK][BSTR];
    __shared__ __nv_bfloat16 Bl[2][BK][BSTR];
    __shared__ float sBias[128];
    __shared__ float sVsel[128];

    const int tid  = threadIdx.x;
    const int lane = tid & 31;
    const int wid  = tid >> 5;
    const int wm   = wid & 3;
    const int wn   = wid >> 2;
    const int m0   = bid * 128;
    const int lda1 = KT1 * BK;
    const int lda2 = KT2 * BK;
    const int KT   = KT1 + KT2;

    if (tid < 128) {
        sBias[tid] = bias[tid];
        if (BIAS_SEL) sVsel[tid] = vsel[tid];
    }

    const int arow0 = tid >> 2;
    const int ac4   = (tid & 3) << 2;
    const int brow0 = tid >> 5;
    const int bn4   = (tid & 31) << 2;

    float4 rA[2], rB[2];

    auto loadTile = [&](int t) {
        const bool first = (t < KT1);
        #pragma unroll
        for (int i = 0; i < 2; i++) {
            int row = arow0 + i * 64;
            int m = m0 + row;
            float4 v = make_float4(0.f, 0.f, 0.f, 0.f);
            if (m < M) {
                const float* p = first ? (A1 + (size_t)m * lda1 + t * BK + ac4)
                                       : (A2 + (size_t)m * lda2 + (t - KT1) * BK + ac4);
                v = *(const float4*)p;
            }
            rA[i] = v;
        }
        #pragma unroll
        for (int i = 0; i < 2; i++) {
            int row = brow0 + i * 8;
            const float* p = first ? (B1 + (size_t)(t * BK + row) * 128 + bn4)
                                   : (B2 + (size_t)((t - KT1) * BK + row) * 128 + bn4);
            rB[i] = *(const float4*)p;
        }
    };
    auto storeTile = [&](int buf) {
        #pragma unroll
        for (int i = 0; i < 2; i++) {
            int row = arow0 + i * 64;
            const float* v = &rA[i].x;
            __nv_bfloat16 h[4], l[4];
            #pragma unroll
            for (int j = 0; j < 4; j++) split_f32(v[j], h[j], l[j]);
            *(uint2*)&Ah[buf][row][ac4] = make_uint2(pack_bf16(h[0], h[1]), pack_bf16(h[2], h[3]));
            *(uint2*)&Al[buf][row][ac4] = make_uint2(pack_bf16(l[0], l[1]), pack_bf16(l[2], l[3]));
        }
        #pragma unroll
        for (int i = 0; i < 2; i++) {
            int row = brow0 + i * 8;
            const float* v = &rB[i].x;
            __nv_bfloat16 h[4], l[4];
            #pragma unroll
            for (int j = 0; j < 4; j++) split_f32(v[j], h[j], l[j]);
            *(uint2*)&Bh[buf][row][bn4] = make_uint2(pack_bf16(h[0], h[1]), pack_bf16(h[2], h[3]));
            *(uint2*)&Bl[buf][row][bn4] = make_uint2(pack_bf16(l[0], l[1]), pack_bf16(l[2], l[3]));
        }
    };

    float d[2][8][4];
    #pragma unroll
    for (int mt = 0; mt < 2; mt++)
        #pragma unroll
        for (int nt = 0; nt < 8; nt++)
            #pragma unroll
            for (int j = 0; j < 4; j++) d[mt][nt][j] = 0.f;

    const int ar = lane & 15;
    const int ac = (lane >> 4) << 3;
    const int br = lane & 15;
    const int bc = wn * 64 + ((lane >> 4) << 3);

    loadTile(0);
    storeTile(0);
    __syncthreads();

    for (int t = 0; t < KT; t++) {
        const int cb = t & 1;
        if (t + 1 < KT) loadTile(t + 1);

        uint32_t fah[2][4], fal[2][4];
        #pragma unroll
        for (int mt = 0; mt < 2; mt++) {
            int row = wm * 32 + mt * 16 + ar;
            ldsm_x4(fah[mt], (uint32_t)__cvta_generic_to_shared(&Ah[cb][row][ac]));
            ldsm_x4(fal[mt], (uint32_t)__cvta_generic_to_shared(&Al[cb][row][ac]));
        }
        #pragma unroll
        for (int ntp = 0; ntp < 4; ntp++) {
            uint32_t fbh[4], fbl[4];
            ldsm_x4_t(fbh, (uint32_t)__cvta_generic_to_shared(&Bh[cb][br][bc + ntp * 16]));
            ldsm_x4_t(fbl, (uint32_t)__cvta_generic_to_shared(&Bl[cb][br][bc + ntp * 16]));
            #pragma unroll
            for (int mt = 0; mt < 2; mt++) {
                mma_bf16(d[mt][2 * ntp],     fah[mt], fbh);
                mma_bf16(d[mt][2 * ntp],     fal[mt], fbh);
                mma_bf16(d[mt][2 * ntp],     fah[mt], fbl);
                mma_bf16(d[mt][2 * ntp + 1], fah[mt], fbh + 2);
                mma_bf16(d[mt][2 * ntp + 1], fal[mt], fbh + 2);
                mma_bf16(d[mt][2 * ntp + 1], fah[mt], fbl + 2);
            }
        }
        if (t + 1 < KT) storeTile((t + 1) & 1);
        __syncthreads();
    }

    const int rb  = m0 + wm * 32 + (lane >> 2);
    const int cb0 = wn * 64 + (lane & 3) * 2;
    #pragma unroll
    for (int mt = 0; mt < 2; mt++) {
        #pragma unroll
        for (int h = 0; h < 2; h++) {
            int m = rb + mt * 16 + h * 8;
            if (m >= M) continue;
            float sel = 0.f;
            if (BIAS_SEL) sel = (deg[m] > 0) ? 1.f : 0.f;
            #pragma unroll
            for (int nt = 0; nt < 8; nt++) {
                int col = cb0 + nt * 8;
                float x = d[mt][nt][h * 2 + 0] + sBias[col];
                float y = d[mt][nt][h * 2 + 1] + sBias[col + 1];
                if (BIAS_SEL) { x += sel * sVsel[col]; y += sel * sVsel[col + 1]; }
                if (RELU) { x = fmaxf(x, 0.f); y = fmaxf(y, 0.f); }
                *(float2*)&C[(size_t)m * 128 + col] = make_float2(x, y);
            }
        }
    }
}

template<bool BIAS_SEL, bool RELU>
__global__ void __launch_bounds__(256)
gemm128_kernel(const float* A1, const float* A2, const float* B1, const float* B2,
               float* C, const float* bias, const float* vsel, const int* deg,
               int M, int KT1, int KT2) {
    gemm128_body<BIAS_SEL, RELU>(A1, A2, B1, B2, C, bias, vsel, deg, M, KT1, KT2, blockIdx.x);
}

// ---------------- fused kernels (intra-launch overlap) ----------------
// fusedA: GEMM4 (movie_x) || deg || vec.  mod-4 interleave: gemm on bid%4==0.
__global__ void __launch_bounds__(256)
fusedA_kernel(const float* __restrict__ movie_feats, const float* __restrict__ Wm, const float* __restrict__ bm,
              float* __restrict__ movie_x,
              const int* __restrict__ src, const int* __restrict__ dst,
              int* __restrict__ du, int* __restrict__ dm,
              const float* __restrict__ user_init, const float* __restrict__ Wl1_um,
              const float* __restrict__ Wr1_mu, const float* __restrict__ bl1_mu,
              float* __restrict__ vecs,
              int GA, int DEGB) {
    int bid = blockIdx.x;
    int q = bid >> 2, r = bid & 3;
    if (r == 0 && q < GA) {
        gemm128_body<false, false>(movie_feats, nullptr, Wm, nullptr, movie_x,
                                   bm, nullptr, nullptr, cNM, cFD / BK, 0, q);
    } else {
        int before = min((bid + 3) >> 2, GA);
        int did = bid - before;
        if (did < DEGB) deg_body(src, dst, du, dm, cE, did, DEGB);
        else            vec_body(user_init, Wl1_um, Wr1_mu, bl1_mu, vecs);
    }
}

// fusedB: GEMM5 (movie_h) || scatter.  mod-4 interleave.
__global__ void __launch_bounds__(256)
fusedB_kernel(const float* __restrict__ movie_x, const float* __restrict__ Wr1_um,
              float* __restrict__ movie_h,
              const float* __restrict__ bl1_um, const float* __restrict__ vsel, const int* __restrict__ deg_m,
              const int* __restrict__ src, const int* __restrict__ dst,
              int* __restrict__ curU, int* __restrict__ curM,
              int* __restrict__ csrU, int* __restrict__ csrM,
              int GA, int SCB) {
    int bid = blockIdx.x;
    int q = bid >> 2, r = bid & 3;
    if (r == 0 && q < GA) {
        gemm128_body<true, true>(movie_x, nullptr, Wr1_um, nullptr, movie_h,
                                 bl1_um, vsel, deg_m, cNM, cH / BK, 0, q);
    } else {
        int before = min((bid + 3) >> 2, GA);
        int did = bid - before;
        if (did < SCB) scatter_body(src, dst, curU, curM, csrU, csrM, cE, did, SCB);
    }
}

// fusedC: GEMM10 (user_o) || agg_movie (fp32).  mod-2 interleave.
__global__ void __launch_bounds__(256)
fusedC_kernel(const float* __restrict__ aggU2, const float* __restrict__ user_h,
              const float* __restrict__ Wl2_mu, const float* __restrict__ Wr2_mu,
              float* __restrict__ user_o, const float* __restrict__ bl2_mu,
              const int* __restrict__ offM, const int* __restrict__ csrM,
              float* __restrict__ aggM2,
              int GA, int AGB) {
    int bid = blockIdx.x;
    int q = bid >> 1, r = bid & 1;
    if (r == 0 && q < GA) {
        gemm128_body<false, false>(aggU2, user_h, Wl2_mu, Wr2_mu, user_o,
                                   bl2_mu, nullptr, nullptr, cNU, cH / BK, cH / BK, q);
    } else {
        int before = min((bid + 1) >> 1, GA);
        int aid = bid - before;
        if (aid < AGB) agg_movie_body(offM, csrM, user_h, aggM2, cNM, aid, AGB);
    }
}

// ---------------- final edge dot products (fp32) ----------------
__global__ void dot_kernel(const int* __restrict__ lu, const int* __restrict__ lm,
                           const float* __restrict__ U, const float* __restrict__ Mo,
                           float* __restrict__ out, int EL) {
    int w    = (blockIdx.x * blockDim.x + threadIdx.x) >> 5;
    int lane = threadIdx.x & 31;
    int nw   = (gridDim.x * blockDim.x) >> 5;
    for (int i = w; i < EL; i += nw) {
        int u = lu[i];
        int m = lm[i];
        float4 a = ((const float4*)(U  + (size_t)u * 128))[lane];
        float4 b = ((const float4*)(Mo + (size_t)m * 128))[lane];
        float p = a.x * b.x + a.y * b.y + a.z * b.z + a.w * b.w;
        #pragma unroll
        for (int off = 16; off > 0; off >>= 1)
            p += __shfl_xor_sync(0xFFFFFFFFu, p, off);
        if (lane == 0) out[i] = p;
    }
}

// ---------------- launch ----------------
extern "C" void kernel_launch(void* const* d_in, const int* in_sizes, int n_in,
                              void* d_out, int out_size) {
    const float* movie_feats = (const float*)d_in[0];
    const float* user_init   = (const float*)d_in[1];
    const int*   edge_src    = (const int*)d_in[2];
    const int*   edge_dst    = (const int*)d_in[3];
    const int*   lbl_user    = (const int*)d_in[4];
    const int*   lbl_movie   = (const int*)d_in[5];
    const int wi = (n_in >= 21) ? 7 : 6;
    const float* Wm     = (const float*)d_in[wi + 0];
    const float* bm     = (const float*)d_in[wi + 1];
    const float* Wl1_um = (const float*)d_in[wi + 2];
    const float* bl1_um = (const float*)d_in[wi + 3];
    const float* Wr1_um = (const float*)d_in[wi + 4];
    const float* Wl1_mu = (const float*)d_in[wi + 5];
    const float* bl1_mu = (const float*)d_in[wi + 6];
    const float* Wr1_mu = (const float*)d_in[wi + 7];
    const float* Wl2_um = (const float*)d_in[wi + 8];
    const float* bl2_um = (const float*)d_in[wi + 9];
    const float* Wr2_um = (const float*)d_in[wi + 10];
    const float* Wl2_mu = (const float*)d_in[wi + 11];
    const float* bl2_mu = (const float*)d_in[wi + 12];
    const float* Wr2_mu = (const float*)d_in[wi + 13];
    float* out = (float*)d_out;

    float *movie_x, *movie_h, *user_h, *aggU1, *aggU2, *aggM2, *movie_o, *user_o, *vecs;
    int *deg_u, *deg_m, *offU, *offM, *curU, *curM, *csrU, *csrM, *partU, *partM;
    cudaGetSymbolAddress((void**)&movie_x, g_movie_x);
    cudaGetSymbolAddress((void**)&movie_h, g_movie_h);
    cudaGetSymbolAddress((void**)&user_h,  g_user_h);
    cudaGetSymbolAddress((void**)&aggU1,   g_aggU1);
    cudaGetSymbolAddress((void**)&aggU2,   g_aggU2);
    cudaGetSymbolAddress((void**)&aggM2,   g_aggM2);
    cudaGetSymbolAddress((void**)&movie_o, g_movie_o);
    cudaGetSymbolAddress((void**)&user_o,  g_user_o);
    cudaGetSymbolAddress((void**)&vecs,    g_vecs);
    cudaGetSymbolAddress((void**)&deg_u,   g_deg_u);
    cudaGetSymbolAddress((void**)&deg_m,   g_deg_m);
    cudaGetSymbolAddress((void**)&offU,    g_offU);
    cudaGetSymbolAddress((void**)&offM,    g_offM);
    cudaGetSymbolAddress((void**)&curU,    g_curU);
    cudaGetSymbolAddress((void**)&curM,    g_curM);
    cudaGetSymbolAddress((void**)&csrU,    g_csrU);
    cudaGetSymbolAddress((void**)&csrM,    g_csrM);
    cudaGetSymbolAddress((void**)&partU,   g_partU);
    cudaGetSymbolAddress((void**)&partM,   g_partM);

    const int GM = (cNM + 127) / 128;   // 625
    const int GU = (cNU + 127) / 128;   // 1563

    // 1) zero degree counters
    zero_i_kernel<<<256, 256>>>(deg_u, cNU);
    zero_i_kernel<<<128, 256>>>(deg_m, cNM);

    // 2) fusedA: GEMM4 || deg || vec
    const int DEGB = 2048;
    fusedA_kernel<<<GM + DEGB + 1, 256>>>(movie_feats, Wm, bm, movie_x,
                                          edge_src, edge_dst, deg_u, deg_m,
                                          user_init, Wl1_um, Wr1_mu, bl1_mu, vecs,
                                          GM, DEGB);

    // 3) CSR offsets
    partial_kernel<<<TU + TM, 256>>>(deg_u, deg_m, partU, partM);
    scanpart_kernel<<<2, 256>>>(partU, partM);
    phase3_kernel<<<TU + TM, 256>>>(deg_u, deg_m, partU, partM, offU, curU, offM, curM);

    // 4) fusedB: GEMM5 || scatter
    const int SCB = 2048;
    fusedB_kernel<<<GM + SCB, 256>>>(movie_x, Wr1_um, movie_h,
                                     bl1_um, vecs, deg_m,
                                     edge_src, edge_dst, curU, curM, csrU, csrM,
                                     GM, SCB);

    // 5) user-side aggregation (fp32 gathers)
    agg_user_kernel<<<4736, 256>>>(offU, csrU, movie_x, movie_h, aggU1, aggU2, cNU);

    // 6) GEMM7: user_h = relu(aggU1 @ Wl1_mu + cb1)
    gemm128_kernel<false, true><<<GU, 256>>>(
        aggU1, nullptr, Wl1_mu, nullptr, user_h, vecs + cH, nullptr, nullptr, cNU, cH / BK, 0);

    // 7) fusedC: GEMM10 (user_o) || agg_movie (fp32)
    const int AGB = 2048;
    int gridC = (2 * GU > GU + AGB) ? 2 * GU : GU + AGB;
    fusedC_kernel<<<gridC, 256>>>(aggU2, user_h, Wl2_mu, Wr2_mu, user_o, bl2_mu,
                                  offM, csrM, aggM2, GU, AGB);

    // 8) GEMM9: movie_o = aggM2 @ Wl2_um + bl2_um + movie_h @ Wr2_um
    gemm128_kernel<false, false><<<GM, 256>>>(
        aggM2, movie_h, Wl2_um, Wr2_um, movie_o, bl2_um, nullptr, nullptr, cNM, cH / BK, cH / BK);

    // 9) final dot products
    dot_kernel<<<4736, 256>>>(lbl_user, lbl_movie, user_o, movie_o, out, cEL);

    (void)in_sizes; (void)out_size;
}

// round 6
// speedup vs baseline: 2.6649x; 1.0224x over previous
#include <cuda_runtime.h>
#include <cuda_bf16.h>
#include <cstddef>
#include <cstdint>

// Problem constants
#define cH   128
#define cNU  200000
#define cNM  80000
#define cE   2000000
#define cEL  500000
#define cFD  512

#define TILE 1024
#define TU   ((cNU + TILE - 1) / TILE)   // 196
#define TM   ((cNM + TILE - 1) / TILE)   // 79

// ---------------- scratch (device globals) ----------------
__device__ float g_movie_x[(size_t)cNM * cH];
__device__ float g_movie_h[(size_t)cNM * cH];
__device__ float g_P1[(size_t)cNM * cH];      // movie_x @ Wl1_mu
__device__ float g_P2[(size_t)cNM * cH];      // movie_h @ Wl2_mu
__device__ float g_user_h [(size_t)cNU * cH];
__device__ float g_aggP2 [(size_t)cNU * cH];  // mean of P2 rows per user
__device__ float g_aggM2 [(size_t)cNM * cH];  // mean of user_h rows per movie
__device__ float g_movie_o[(size_t)cNM * cH];
__device__ float g_user_o [(size_t)cNU * cH];
__device__ int   g_deg_u[cNU];
__device__ int   g_deg_m[cNM];
__device__ int   g_offU[cNU + 1];
__device__ int   g_offM[cNM + 1];
__device__ int   g_curU[cNU];
__device__ int   g_curM[cNM];
__device__ int   g_csrU[cE];
__device__ int   g_csrM[cE];
__device__ int   g_partU[TU];
__device__ int   g_partM[TM];
__device__ float g_vecs[2 * cH];   // [0:128) vsel ; [128:256) cb1
__device__ float g_zero[cH];       // zero-initialized

// ---------------- small utility kernels ----------------
__global__ void zero_i_kernel(int* p, int n) {
    int i = blockIdx.x * blockDim.x + threadIdx.x;
    int stride = gridDim.x * blockDim.x;
    for (; i < n; i += stride) p[i] = 0;
}

// ---- device bodies ----
__device__ __forceinline__ void deg_body(const int* __restrict__ src, const int* __restrict__ dst,
                                         int* __restrict__ du, int* __restrict__ dm,
                                         int E, int vbid, int vgrid) {
    int i = vbid * 256 + threadIdx.x;
    int stride = vgrid * 256;
    for (; i < E; i += stride) {
        atomicAdd(&du[src[i]], 1);
        atomicAdd(&dm[dst[i]], 1);
    }
}

__device__ __forceinline__ void scatter_body(const int* __restrict__ src, const int* __restrict__ dst,
                                             int* __restrict__ curU, int* __restrict__ curM,
                                             int* __restrict__ csrU, int* __restrict__ csrM,
                                             int E, int vbid, int vgrid) {
    int i = vbid * 256 + threadIdx.x;
    int stride = vgrid * 256;
    for (; i < E; i += stride) {
        int s = src[i];
        int d = dst[i];
        int p = atomicAdd(&curU[s], 1);
        csrU[p] = d;
        int q = atomicAdd(&curM[d], 1);
        csrM[q] = s;
    }
}

__device__ __forceinline__ void vec_body(const float* __restrict__ user_init,
                                         const float* __restrict__ Wl1_um,
                                         const float* __restrict__ Wr1_mu,
                                         const float* __restrict__ bl1_mu,
                                         float* __restrict__ vecs) {
    int j = threadIdx.x;
    if (j >= cH) return;
    float s1 = 0.f, s2 = 0.f;
    for (int k = 0; k < cH; k++) {
        float u = user_init[k];
        s1 = fmaf(u, Wl1_um[k * cH + j], s1);
        s2 = fmaf(u, Wr1_mu[k * cH + j], s2);
    }
    vecs[j]      = s1;
    vecs[cH + j] = bl1_mu[j] + s2;
}

__device__ __forceinline__ void agg_movie_body(const int* __restrict__ off, const int* __restrict__ csr,
                                               const float* __restrict__ uh,
                                               float* __restrict__ aM2, int NM, int vbid, int vgrid) {
    int w    = vbid * 8 + (threadIdx.x >> 5);
    int lane = threadIdx.x & 31;
    int nw   = vgrid * 8;
    for (int m = w; m < NM; m += nw) {
        int s = off[m], e = off[m + 1];
        float4 a1 = make_float4(0.f, 0.f, 0.f, 0.f);
        float4 a2 = make_float4(0.f, 0.f, 0.f, 0.f);
        int i = s;
        for (; i + 1 < e; i += 2) {
            int d0 = csr[i];
            int d1 = csr[i + 1];
            float4 v0 = ((const float4*)(uh + (size_t)d0 * 128))[lane];
            float4 v1 = ((const float4*)(uh + (size_t)d1 * 128))[lane];
            a1.x += v0.x; a1.y += v0.y; a1.z += v0.z; a1.w += v0.w;
            a2.x += v1.x; a2.y += v1.y; a2.z += v1.z; a2.w += v1.w;
        }
        if (i < e) {
            int d0 = csr[i];
            float4 v0 = ((const float4*)(uh + (size_t)d0 * 128))[lane];
            a1.x += v0.x; a1.y += v0.y; a1.z += v0.z; a1.w += v0.w;
        }
        float sc = (e > s) ? 1.f / (float)(e - s) : 0.f;
        float4 o = make_float4((a1.x + a2.x) * sc, (a1.y + a2.y) * sc, (a1.z + a2.z) * sc, (a1.w + a2.w) * sc);
        ((float4*)(aM2 + (size_t)m * 128))[lane] = o;
    }
}

// ---- parallel scan ----
__global__ void partial_kernel(const int* __restrict__ degU, const int* __restrict__ degM,
                               int* __restrict__ partU, int* __restrict__ partM) {
    int b = blockIdx.x;
    const int* deg; int* part; int n, tile;
    if (b < TU) { deg = degU; part = partU; n = cNU; tile = b; }
    else        { deg = degM; part = partM; n = cNM; tile = b - TU; }

    int tid = threadIdx.x;
    int base = tile * TILE + tid * 4;
    int s = 0;
    #pragma unroll
    for (int j = 0; j < 4; j++) {
        int i = base + j;
        if (i < n) s += deg[i];
    }
    __shared__ int wsum[8];
    int lane = tid & 31, wid = tid >> 5;
    #pragma unroll
    for (int o = 16; o > 0; o >>= 1) s += __shfl_down_sync(0xffffffffu, s, o);
    if (lane == 0) wsum[wid] = s;
    __syncthreads();
    if (tid == 0) {
        int t = 0;
        #pragma unroll
        for (int w = 0; w < 8; w++) t += wsum[w];
        part[tile] = t;
    }
}

__global__ void scanpart_kernel(int* __restrict__ partU, int* __restrict__ partM) {
    int* part = (blockIdx.x == 0) ? partU : partM;
    int cnt   = (blockIdx.x == 0) ? TU : TM;
    int tid = threadIdx.x, lane = tid & 31, wid = tid >> 5;
    __shared__ int wsum[8];
    int v = (tid < cnt) ? part[tid] : 0;
    int x = v;
    #pragma unroll
    for (int o = 1; o < 32; o <<= 1) {
        int t = __shfl_up_sync(0xffffffffu, x, o);
        if (lane >= o) x += t;
    }
    if (lane == 31) wsum[wid] = x;
    __syncthreads();
    if (wid == 0) {
        int s = (lane < 8) ? wsum[lane] : 0;
        #pragma unroll
        for (int o = 1; o < 8; o <<= 1) {
            int t = __shfl_up_sync(0xffffffffu, s, o);
            if (lane >= o) s += t;
        }
        if (lane < 8) wsum[lane] = s;
    }
    __syncthreads();
    int incl = x + ((wid > 0) ? wsum[wid - 1] : 0);
    if (tid < cnt) part[tid] = incl - v;
}

__global__ void phase3_kernel(const int* __restrict__ degU, const int* __restrict__ degM,
                              const int* __restrict__ partU, const int* __restrict__ partM,
                              int* __restrict__ offU, int* __restrict__ curU,
                              int* __restrict__ offM, int* __restrict__ curM) {
    int b = blockIdx.x;
    const int* deg; const int* part; int* off; int* cur; int n, tile;
    if (b < TU) { deg = degU; part = partU; off = offU; cur = curU; n = cNU; tile = b; }
    else        { deg = degM; part = partM; off = offM; cur = curM; n = cNM; tile = b - TU; }

    int tid = threadIdx.x, lane = tid & 31, wid = tid >> 5;
    if (b == 0 && tid == 0) { offU[cNU] = cE; offM[cNM] = cE; }

    int base = tile * TILE + tid * 4;
    int v[4];
    int s = 0;
    #pragma unroll
    for (int j = 0; j < 4; j++) {
        int i = base + j;
        v[j] = (i < n) ? deg[i] : 0;
        s += v[j];
    }
    __shared__ int wsum[8];
    int x = s;
    #pragma unroll
    for (int o = 1; o < 32; o <<= 1) {
        int t = __shfl_up_sync(0xffffffffu, x, o);
        if (lane >= o) x += t;
    }
    if (lane == 31) wsum[wid] = x;
    __syncthreads();
    if (wid == 0) {
        int t = (lane < 8) ? wsum[lane] : 0;
        #pragma unroll
        for (int o = 1; o < 8; o <<= 1) {
            int u = __shfl_up_sync(0xffffffffu, t, o);
            if (lane >= o) t += u;
        }
        if (lane < 8) wsum[lane] = t;
    }
    __syncthreads();
    int excl = x - s + ((wid > 0) ? wsum[wid - 1] : 0);
    int run = part[tile] + excl;
    #pragma unroll
    for (int j = 0; j < 4; j++) {
        int i = base + j;
        if (i < n) { off[i] = run; cur[i] = run; run += v[j]; }
    }
}

// ---------------- user-side aggregation of P1,P2 with fused relu epilogue ----------------
// user_h = relu(mean P1[d] + cb1) ; aggP2 = mean P2[d]
__global__ void agg_user_kernel(const int* __restrict__ off, const int* __restrict__ csr,
                                const float* __restrict__ P1, const float* __restrict__ P2,
                                const float* __restrict__ vecs,
                                float* __restrict__ user_h, float* __restrict__ aggP2, int NU) {
    int w    = (blockIdx.x * blockDim.x + threadIdx.x) >> 5;
    int lane = threadIdx.x & 31;
    int nw   = (gridDim.x * blockDim.x) >> 5;
    float4 c1 = ((const float4*)(vecs + cH))[lane];   // cb1 per-lane slice
    for (int u = w; u < NU; u += nw) {
        int s = off[u], e = off[u + 1];
        float4 a1 = make_float4(0.f, 0.f, 0.f, 0.f);
        float4 a2 = make_float4(0.f, 0.f, 0.f, 0.f);
        float4 a3 = make_float4(0.f, 0.f, 0.f, 0.f);
        float4 a4 = make_float4(0.f, 0.f, 0.f, 0.f);
        int i = s;
        for (; i + 1 < e; i += 2) {
            int d0 = csr[i];
            int d1 = csr[i + 1];
            float4 v0 = ((const float4*)(P1 + (size_t)d0 * 128))[lane];
            float4 w0 = ((const float4*)(P2 + (size_t)d0 * 128))[lane];
            float4 v1 = ((const float4*)(P1 + (size_t)d1 * 128))[lane];
            float4 w1 = ((const float4*)(P2 + (size_t)d1 * 128))[lane];
            a1.x += v0.x; a1.y += v0.y; a1.z += v0.z; a1.w += v0.w;
            a2.x += w0.x; a2.y += w0.y; a2.z += w0.z; a2.w += w0.w;
            a3.x += v1.x; a3.y += v1.y; a3.z += v1.z; a3.w += v1.w;
            a4.x += w1.x; a4.y += w1.y; a4.z += w1.z; a4.w += w1.w;
        }
        if (i < e) {
            int d0 = csr[i];
            float4 v0 = ((const float4*)(P1 + (size_t)d0 * 128))[lane];
            float4 w0 = ((const float4*)(P2 + (size_t)d0 * 128))[lane];
            a1.x += v0.x; a1.y += v0.y; a1.z += v0.z; a1.w += v0.w;
            a2.x += w0.x; a2.y += w0.y; a2.z += w0.z; a2.w += w0.w;
        }
        float sc = (e > s) ? 1.f / (float)(e - s) : 0.f;
        float4 o1 = make_float4(fmaxf((a1.x + a3.x) * sc + c1.x, 0.f),
                                fmaxf((a1.y + a3.y) * sc + c1.y, 0.f),
                                fmaxf((a1.z + a3.z) * sc + c1.z, 0.f),
                                fmaxf((a1.w + a3.w) * sc + c1.w, 0.f));
        float4 o2 = make_float4((a2.x + a4.x) * sc, (a2.y + a4.y) * sc, (a2.z + a4.z) * sc, (a2.w + a4.w) * sc);
        ((float4*)(user_h + (size_t)u * 128))[lane] = o1;
        ((float4*)(aggP2 + (size_t)u * 128))[lane] = o2;
    }
}

// ---------------- tensor-core SGEMM via split-bf16 ----------------
#define BK   16
#define ASTR 24
#define BSTR 136

__device__ __forceinline__ unsigned pack_bf16(__nv_bfloat16 a, __nv_bfloat16 b) {
    __nv_bfloat162 t = __halves2bfloat162(a, b);
    return reinterpret_cast<unsigned&>(t);
}
__device__ __forceinline__ void split_f32(float x, __nv_bfloat16& h, __nv_bfloat16& l) {
    h = __float2bfloat16(x);
    l = __float2bfloat16(x - __bfloat162float(h));
}
__device__ __forceinline__ void ldsm_x4(uint32_t* r, uint32_t addr) {
    asm volatile("ldmatrix.sync.aligned.m8n8.x4.shared.b16 {%0,%1,%2,%3}, [%4];"
                 : "=r"(r[0]), "=r"(r[1]), "=r"(r[2]), "=r"(r[3]) : "r"(addr));
}
__device__ __forceinline__ void ldsm_x4_t(uint32_t* r, uint32_t addr) {
    asm volatile("ldmatrix.sync.aligned.m8n8.x4.trans.shared.b16 {%0,%1,%2,%3}, [%4];"
                 : "=r"(r[0]), "=r"(r[1]), "=r"(r[2]), "=r"(r[3]) : "r"(addr));
}
__device__ __forceinline__ void mma_bf16(float* d, const uint32_t* a, const uint32_t* b) {
    asm volatile("mma.sync.aligned.m16n8k16.row.col.f32.bf16.bf16.f32 "
                 "{%0,%1,%2,%3}, {%4,%5,%6,%7}, {%8,%9}, {%0,%1,%2,%3};"
                 : "+f"(d[0]), "+f"(d[1]), "+f"(d[2]), "+f"(d[3])
                 : "r"(a[0]), "r"(a[1]), "r"(a[2]), "r"(a[3]), "r"(b[0]), "r"(b[1]));
}

template<bool BIAS_SEL, bool RELU, bool ADD_D>
__device__ __forceinline__ void gemm128_body(
    const float* __restrict__ A1, const float* __restrict__ A2,
    const float* __restrict__ B1, const float* __restrict__ B2,
    float* __restrict__ C,
    const float* __restrict__ bias, const float* __restrict__ vsel,
    const int* __restrict__ deg, const float* __restrict__ Dm,
    int M, int KT1, int KT2, int bid) {
    __shared__ __nv_bfloat16 Ah[2][128][ASTR];
    __shared__ __nv_bfloat16 Al[2][128][ASTR];
    __shared__ __nv_bfloat16 Bh[2][BK][BSTR];
    __shared__ __nv_bfloat16 Bl[2][BK][BSTR];
    __shared__ float sBias[128];
    __shared__ float sVsel[128];

    const int tid  = threadIdx.x;
    const int lane = tid & 31;
    const int wid  = tid >> 5;
    const int wm   = wid & 3;
    const int wn   = wid >> 2;
    const int m0   = bid * 128;
    const int lda1 = KT1 * BK;
    const int lda2 = KT2 * BK;
    const int KT   = KT1 + KT2;

    if (tid < 128) {
        sBias[tid] = bias[tid];
        if (BIAS_SEL) sVsel[tid] = vsel[tid];
    }

    const int arow0 = tid >> 2;
    const int ac4   = (tid & 3) << 2;
    const int brow0 = tid >> 5;
    const int bn4   = (tid & 31) << 2;

    float4 rA[2], rB[2];

    auto loadTile = [&](int t) {
        const bool first = (t < KT1);
        #pragma unroll
        for (int i = 0; i < 2; i++) {
            int row = arow0 + i * 64;
            int m = m0 + row;
            float4 v = make_float4(0.f, 0.f, 0.f, 0.f);
            if (m < M) {
                const float* p = first ? (A1 + (size_t)m * lda1 + t * BK + ac4)
                                       : (A2 + (size_t)m * lda2 + (t - KT1) * BK + ac4);
                v = *(const float4*)p;
            }
            rA[i] = v;
        }
        #pragma unroll
        for (int i = 0; i < 2; i++) {
            int row = brow0 + i * 8;
            const float* p = first ? (B1 + (size_t)(t * BK + row) * 128 + bn4)
                                   : (B2 + (size_t)((t - KT1) * BK + row) * 128 + bn4);
            rB[i] = *(const float4*)p;
        }
    };
    auto storeTile = [&](int buf) {
        #pragma unroll
        for (int i = 0; i < 2; i++) {
            int row = arow0 + i * 64;
            const float* v = &rA[i].x;
            __nv_bfloat16 h[4], l[4];
            #pragma unroll
            for (int j = 0; j < 4; j++) split_f32(v[j], h[j], l[j]);
            *(uint2*)&Ah[buf][row][ac4] = make_uint2(pack_bf16(h[0], h[1]), pack_bf16(h[2], h[3]));
            *(uint2*)&Al[buf][row][ac4] = make_uint2(pack_bf16(l[0], l[1]), pack_bf16(l[2], l[3]));
        }
        #pragma unroll
        for (int i = 0; i < 2; i++) {
            int row = brow0 + i * 8;
            const float* v = &rB[i].x;
            __nv_bfloat16 h[4], l[4];
            #pragma unroll
            for (int j = 0; j < 4; j++) split_f32(v[j], h[j], l[j]);
            *(uint2*)&Bh[buf][row][bn4] = make_uint2(pack_bf16(h[0], h[1]), pack_bf16(h[2], h[3]));
            *(uint2*)&Bl[buf][row][bn4] = make_uint2(pack_bf16(l[0], l[1]), pack_bf16(l[2], l[3]));
        }
    };

    float d[2][8][4];
    #pragma unroll
    for (int mt = 0; mt < 2; mt++)
        #pragma unroll
        for (int nt = 0; nt < 8; nt++)
            #pragma unroll
            for (int j = 0; j < 4; j++) d[mt][nt][j] = 0.f;

    const int ar = lane & 15;
    const int ac = (lane >> 4) << 3;
    const int br = lane & 15;
    const int bc = wn * 64 + ((lane >> 4) << 3);

    loadTile(0);
    storeTile(0);
    __syncthreads();

    for (int t = 0; t < KT; t++) {
        const int cb = t & 1;
        if (t + 1 < KT) loadTile(t + 1);

        uint32_t fah[2][4], fal[2][4];
        #pragma unroll
        for (int mt = 0; mt < 2; mt++) {
            int row = wm * 32 + mt * 16 + ar;
            ldsm_x4(fah[mt], (uint32_t)__cvta_generic_to_shared(&Ah[cb][row][ac]));
            ldsm_x4(fal[mt], (uint32_t)__cvta_generic_to_shared(&Al[cb][row][ac]));
        }
        #pragma unroll
        for (int ntp = 0; ntp < 4; ntp++) {
            uint32_t fbh[4], fbl[4];
            ldsm_x4_t(fbh, (uint32_t)__cvta_generic_to_shared(&Bh[cb][br][bc + ntp * 16]));
            ldsm_x4_t(fbl, (uint32_t)__cvta_generic_to_shared(&Bl[cb][br][bc + ntp * 16]));
            #pragma unroll
            for (int mt = 0; mt < 2; mt++) {
                mma_bf16(d[mt][2 * ntp],     fah[mt], fbh);
                mma_bf16(d[mt][2 * ntp],     fal[mt], fbh);
                mma_bf16(d[mt][2 * ntp],     fah[mt], fbl);
                mma_bf16(d[mt][2 * ntp + 1], fah[mt], fbh + 2);
                mma_bf16(d[mt][2 * ntp + 1], fal[mt], fbh + 2);
                mma_bf16(d[mt][2 * ntp + 1], fah[mt], fbl + 2);
            }
        }
        if (t + 1 < KT) storeTile((t + 1) & 1);
        __syncthreads();
    }

    const int rb  = m0 + wm * 32 + (lane >> 2);
    const int cb0 = wn * 64 + (lane & 3) * 2;
    #pragma unroll
    for (int mt = 0; mt < 2; mt++) {
        #pragma unroll
        for (int h = 0; h < 2; h++) {
            int m = rb + mt * 16 + h * 8;
            if (m >= M) continue;
            float sel = 0.f;
            if (BIAS_SEL) sel = (deg[m] > 0) ? 1.f : 0.f;
            #pragma unroll
            for (int nt = 0; nt < 8; nt++) {
                int col = cb0 + nt * 8;
                float x = d[mt][nt][h * 2 + 0] + sBias[col];
                float y = d[mt][nt][h * 2 + 1] + sBias[col + 1];
                if (BIAS_SEL) { x += sel * sVsel[col]; y += sel * sVsel[col + 1]; }
                if (ADD_D) {
                    float2 dv = *(const float2*)&Dm[(size_t)m * 128 + col];
                    x += dv.x; y += dv.y;
                }
                if (RELU) { x = fmaxf(x, 0.f); y = fmaxf(y, 0.f); }
                *(float2*)&C[(size_t)m * 128 + col] = make_float2(x, y);
            }
        }
    }
}

template<bool BIAS_SEL, bool RELU, bool ADD_D>
__global__ void __launch_bounds__(256)
gemm128_kernel(const float* A1, const float* A2, const float* B1, const float* B2,
               float* C, const float* bias, const float* vsel, const int* deg,
               const float* Dm, int M, int KT1, int KT2) {
    gemm128_body<BIAS_SEL, RELU, ADD_D>(A1, A2, B1, B2, C, bias, vsel, deg, Dm, M, KT1, KT2, blockIdx.x);
}

// ---------------- fused kernels ----------------
// fusedA: GEMM4 (movie_x) || deg || vec.
__global__ void __launch_bounds__(256)
fusedA_kernel(const float* __restrict__ movie_feats, const float* __restrict__ Wm, const float* __restrict__ bm,
              float* __restrict__ movie_x,
              const int* __restrict__ src, const int* __restrict__ dst,
              int* __restrict__ du, int* __restrict__ dm,
              const float* __restrict__ user_init, const float* __restrict__ Wl1_um,
              const float* __restrict__ Wr1_mu, const float* __restrict__ bl1_mu,
              float* __restrict__ vecs,
              int GA, int DEGB) {
    int bid = blockIdx.x;
    int q = bid >> 2, r = bid & 3;
    if (r == 0 && q < GA) {
        gemm128_body<false, false, false>(movie_feats, nullptr, Wm, nullptr, movie_x,
                                          bm, nullptr, nullptr, nullptr, cNM, cFD / BK, 0, q);
    } else {
        int before = min((bid + 3) >> 2, GA);
        int did = bid - before;
        if (did < DEGB) deg_body(src, dst, du, dm, cE, did, DEGB);
        else            vec_body(user_init, Wl1_um, Wr1_mu, bl1_mu, vecs);
    }
}

// fusedB: GEMM5 (movie_h) || P1-GEMM || scatter.  gemm blocks on bid%4==0, q<2*GM.
__global__ void __launch_bounds__(256)
fusedB_kernel(const float* __restrict__ movie_x,
              const float* __restrict__ Wr1_um, const float* __restrict__ Wl1_mu,
              float* __restrict__ movie_h, float* __restrict__ P1,
              const float* __restrict__ bl1_um, const float* __restrict__ vsel, const int* __restrict__ deg_m,
              const float* __restrict__ zero,
              const int* __restrict__ src, const int* __restrict__ dst,
              int* __restrict__ curU, int* __restrict__ curM,
              int* __restrict__ csrU, int* __restrict__ csrM,
              int GM_, int GA, int SCB) {
    int bid = blockIdx.x;
    int q = bid >> 2, r = bid & 3;
    if (r == 0 && q < GA) {
        if (q < GM_) {
            gemm128_body<true, true, false>(movie_x, nullptr, Wr1_um, nullptr, movie_h,
                                            bl1_um, vsel, deg_m, nullptr, cNM, cH / BK, 0, q);
        } else {
            gemm128_body<false, false, false>(movie_x, nullptr, Wl1_mu, nullptr, P1,
                                              zero, nullptr, nullptr, nullptr, cNM, cH / BK, 0, q - GM_);
        }
    } else {
        int before = min((bid + 3) >> 2, GA);
        int did = bid - before;
        if (did < SCB) scatter_body(src, dst, curU, curM, csrU, csrM, cE, did, SCB);
    }
}

// fusedC: GEMM10' (user_o = user_h@Wr2_mu + bl2_mu + aggP2) || agg_movie.
__global__ void __launch_bounds__(256)
fusedC_kernel(const float* __restrict__ user_h, const float* __restrict__ Wr2_mu,
              float* __restrict__ user_o, const float* __restrict__ bl2_mu,
              const float* __restrict__ aggP2,
              const int* __restrict__ offM, const int* __restrict__ csrM,
              float* __restrict__ aggM2,
              int GA, int AGB) {
    int bid = blockIdx.x;
    int q = bid >> 1, r = bid & 1;
    if (r == 0 && q < GA) {
        gemm128_body<false, false, true>(user_h, nullptr, Wr2_mu, nullptr, user_o,
                                         bl2_mu, nullptr, nullptr, aggP2, cNU, cH / BK, 0, q);
    } else {
        int before = min((bid + 1) >> 1, GA);
        int aid = bid - before;
        if (aid < AGB) agg_movie_body(offM, csrM, user_h, aggM2, cNM, aid, AGB);
    }
}

// ---------------- final edge dot products ----------------
__global__ void dot_kernel(const int* __restrict__ lu, const int* __restrict__ lm,
                           const float* __restrict__ U, const float* __restrict__ Mo,
                           float* __restrict__ out, int EL) {
    int w    = (blockIdx.x * blockDim.x + threadIdx.x) >> 5;
    int lane = threadIdx.x & 31;
    int nw   = (gridDim.x * blockDim.x) >> 5;
    for (int i = w; i < EL; i += nw) {
        int u = lu[i];
        int m = lm[i];
        float4 a = ((const float4*)(U  + (size_t)u * 128))[lane];
        float4 b = ((const float4*)(Mo + (size_t)m * 128))[lane];
        float p = a.x * b.x + a.y * b.y + a.z * b.z + a.w * b.w;
        #pragma unroll
        for (int off = 16; off > 0; off >>= 1)
            p += __shfl_xor_sync(0xFFFFFFFFu, p, off);
        if (lane == 0) out[i] = p;
    }
}

// ---------------- launch ----------------
extern "C" void kernel_launch(void* const* d_in, const int* in_sizes, int n_in,
                              void* d_out, int out_size) {
    const float* movie_feats = (const float*)d_in[0];
    const float* user_init   = (const float*)d_in[1];
    const int*   edge_src    = (const int*)d_in[2];
    const int*   edge_dst    = (const int*)d_in[3];
    const int*   lbl_user    = (const int*)d_in[4];
    const int*   lbl_movie   = (const int*)d_in[5];
    const int wi = (n_in >= 21) ? 7 : 6;
    const float* Wm     = (const float*)d_in[wi + 0];
    const float* bm     = (const float*)d_in[wi + 1];
    const float* Wl1_um = (const float*)d_in[wi + 2];
    const float* bl1_um = (const float*)d_in[wi + 3];
    const float* Wr1_um = (const float*)d_in[wi + 4];
    const float* Wl1_mu = (const float*)d_in[wi + 5];
    const float* bl1_mu = (const float*)d_in[wi + 6];
    const float* Wr1_mu = (const float*)d_in[wi + 7];
    const float* Wl2_um = (const float*)d_in[wi + 8];
    const float* bl2_um = (const float*)d_in[wi + 9];
    const float* Wr2_um = (const float*)d_in[wi + 10];
    const float* Wl2_mu = (const float*)d_in[wi + 11];
    const float* bl2_mu = (const float*)d_in[wi + 12];
    const float* Wr2_mu = (const float*)d_in[wi + 13];
    float* out = (float*)d_out;

    float *movie_x, *movie_h, *P1, *P2, *user_h, *aggP2, *aggM2, *movie_o, *user_o, *vecs, *zero;
    int *deg_u, *deg_m, *offU, *offM, *curU, *curM, *csrU, *csrM, *partU, *partM;
    cudaGetSymbolAddress((void**)&movie_x, g_movie_x);
    cudaGetSymbolAddress((void**)&movie_h, g_movie_h);
    cudaGetSymbolAddress((void**)&P1,      g_P1);
    cudaGetSymbolAddress((void**)&P2,      g_P2);
    cudaGetSymbolAddress((void**)&user_h,  g_user_h);
    cudaGetSymbolAddress((void**)&aggP2,   g_aggP2);
    cudaGetSymbolAddress((void**)&aggM2,   g_aggM2);
    cudaGetSymbolAddress((void**)&movie_o, g_movie_o);
    cudaGetSymbolAddress((void**)&user_o,  g_user_o);
    cudaGetSymbolAddress((void**)&vecs,    g_vecs);
    cudaGetSymbolAddress((void**)&zero,    g_zero);
    cudaGetSymbolAddress((void**)&deg_u,   g_deg_u);
    cudaGetSymbolAddress((void**)&deg_m,   g_deg_m);
    cudaGetSymbolAddress((void**)&offU,    g_offU);
    cudaGetSymbolAddress((void**)&offM,    g_offM);
    cudaGetSymbolAddress((void**)&curU,    g_curU);
    cudaGetSymbolAddress((void**)&curM,    g_curM);
    cudaGetSymbolAddress((void**)&csrU,    g_csrU);
    cudaGetSymbolAddress((void**)&csrM,    g_csrM);
    cudaGetSymbolAddress((void**)&partU,   g_partU);
    cudaGetSymbolAddress((void**)&partM,   g_partM);

    const int GM = (cNM + 127) / 128;   // 625
    const int GU = (cNU + 127) / 128;   // 1563

    // 1) zero degree counters
    zero_i_kernel<<<256, 256>>>(deg_u, cNU);
    zero_i_kernel<<<128, 256>>>(deg_m, cNM);

    // 2) fusedA: GEMM4 || deg || vec
    const int DEGB = 2048;
    fusedA_kernel<<<GM + DEGB + 1, 256>>>(movie_feats, Wm, bm, movie_x,
                                          edge_src, edge_dst, deg_u, deg_m,
                                          user_init, Wl1_um, Wr1_mu, bl1_mu, vecs,
                                          GM, DEGB);

    // 3) CSR offsets
    partial_kernel<<<TU + TM, 256>>>(deg_u, deg_m, partU, partM);
    scanpart_kernel<<<2, 256>>>(partU, partM);
    phase3_kernel<<<TU + TM, 256>>>(deg_u, deg_m, partU, partM, offU, curU, offM, curM);

    // 4) fusedB: GEMM5 || P1 || scatter
    {
        const int GA = 2 * GM;            // 1250 gemm blocks
        const int grid = 4 * GA;          // ensures all gemm bids fit
        const int SCB = grid - GA;        // scatter virtual-grid
        fusedB_kernel<<<grid, 256>>>(movie_x, Wr1_um, Wl1_mu, movie_h, P1,
                                     bl1_um, vecs, deg_m, zero,
                                     edge_src, edge_dst, curU, curM, csrU, csrM,
                                     GM, GA, SCB);
    }

    // 5) P2 = movie_h @ Wl2_mu
    gemm128_kernel<false, false, false><<<GM, 256>>>(
        movie_h, nullptr, Wl2_mu, nullptr, P2, zero, nullptr, nullptr, nullptr, cNM, cH / BK, 0);

    // 6) user-side aggregation: user_h = relu(meanP1 + cb1), aggP2 = meanP2
    agg_user_kernel<<<4736, 256>>>(offU, csrU, P1, P2, vecs, user_h, aggP2, cNU);

    // 7) fusedC: GEMM10' (user_o) || agg_movie
    {
        const int gridC = 2 * GU;
        const int AGB = gridC - GU;
        fusedC_kernel<<<gridC, 256>>>(user_h, Wr2_mu, user_o, bl2_mu, aggP2,
                                      offM, csrM, aggM2, GU, AGB);
    }

    // 8) GEMM9: movie_o = aggM2 @ Wl2_um + bl2_um + movie_h @ Wr2_um
    gemm128_kernel<false, false, false><<<GM, 256>>>(
        aggM2, movie_h, Wl2_um, Wr2_um, movie_o, bl2_um, nullptr, nullptr, nullptr, cNM, cH / BK, cH / BK);

    // 9) final dot products
    dot_kernel<<<4736, 256>>>(lbl_user, lbl_movie, user_o, movie_o, out, cEL);

    (void)in_sizes; (void)out_size;
}